// round 1
// baseline (speedup 1.0000x reference)
#include <cuda_runtime.h>
#include <math.h>

// Problem constants (fixed by the dataset)
#define D_MODEL   1024
#define HEADS     16
#define HEAD_DIM  64
#define BATCH     2
#define SEQ       2048
#define M_TOTAL   (BATCH * SEQ)       // 4096 rows for projection GEMMs

// Scratch: device globals (no allocations allowed)
__device__ float g_q[M_TOTAL * D_MODEL];
__device__ float g_k[M_TOTAL * D_MODEL];
__device__ float g_v[M_TOTAL * D_MODEL];
__device__ float g_attn[M_TOTAL * D_MODEL];

// ----------------------------------------------------------------------------
// GEMM: C[M,N] = A[M,K] @ W[N,K]^T + bias[N]   (torch Linear)
// M=4096, N=K=1024. Block tile 128x128, K-tile 16, 256 threads, 8x8 microtile.
// ----------------------------------------------------------------------------
__global__ __launch_bounds__(256) void gemm_nt_bias(
    const float* __restrict__ A,
    const float* __restrict__ W,
    const float* __restrict__ bias,
    float* __restrict__ C)
{
    const int K = D_MODEL;
    const int N = D_MODEL;

    __shared__ float As[16][132];   // stored transposed: As[k][m]
    __shared__ float Bs[16][132];   // Bs[k][n]

    const int tid = threadIdx.x;
    const int tm = tid >> 4;        // 0..15
    const int tn = tid & 15;        // 0..15
    const int bm = blockIdx.y;
    const int bn = blockIdx.x;

    const float* Ablk = A + (size_t)bm * 128 * K;
    const float* Wblk = W + (size_t)bn * 128 * K;

    float acc[8][8];
    #pragma unroll
    for (int i = 0; i < 8; i++)
        #pragma unroll
        for (int j = 0; j < 8; j++)
            acc[i][j] = 0.0f;

    for (int kt = 0; kt < K; kt += 16) {
        // Load 128x16 tiles of A and W (2 float4 per thread per matrix)
        #pragma unroll
        for (int l = 0; l < 2; l++) {
            int idx = tid + l * 256;          // 0..511
            int r   = idx >> 2;               // 0..127
            int c4  = (idx & 3) * 4;          // 0,4,8,12
            float4 a = *(const float4*)(Ablk + (size_t)r * K + kt + c4);
            As[c4 + 0][r] = a.x;
            As[c4 + 1][r] = a.y;
            As[c4 + 2][r] = a.z;
            As[c4 + 3][r] = a.w;
            float4 b = *(const float4*)(Wblk + (size_t)r * K + kt + c4);
            Bs[c4 + 0][r] = b.x;
            Bs[c4 + 1][r] = b.y;
            Bs[c4 + 2][r] = b.z;
            Bs[c4 + 3][r] = b.w;
        }
        __syncthreads();

        #pragma unroll
        for (int kk = 0; kk < 16; kk++) {
            float a[8], b[8];
            *(float4*)(a)     = *(const float4*)&As[kk][tm * 8];
            *(float4*)(a + 4) = *(const float4*)&As[kk][tm * 8 + 4];
            *(float4*)(b)     = *(const float4*)&Bs[kk][tn * 8];
            *(float4*)(b + 4) = *(const float4*)&Bs[kk][tn * 8 + 4];
            #pragma unroll
            for (int i = 0; i < 8; i++)
                #pragma unroll
                for (int j = 0; j < 8; j++)
                    acc[i][j] = fmaf(a[i], b[j], acc[i][j]);
        }
        __syncthreads();
    }

    // Epilogue: add bias, store
    float4 bv0 = *(const float4*)&bias[bn * 128 + tn * 8];
    float4 bv1 = *(const float4*)&bias[bn * 128 + tn * 8 + 4];
    #pragma unroll
    for (int i = 0; i < 8; i++) {
        int row = bm * 128 + tm * 8 + i;
        float4 o0, o1;
        o0.x = acc[i][0] + bv0.x; o0.y = acc[i][1] + bv0.y;
        o0.z = acc[i][2] + bv0.z; o0.w = acc[i][3] + bv0.w;
        o1.x = acc[i][4] + bv1.x; o1.y = acc[i][5] + bv1.y;
        o1.z = acc[i][6] + bv1.z; o1.w = acc[i][7] + bv1.w;
        *(float4*)&C[(size_t)row * N + bn * 128 + tn * 8]     = o0;
        *(float4*)&C[(size_t)row * N + bn * 128 + tn * 8 + 4] = o1;
    }
}

// ----------------------------------------------------------------------------
// Flash attention, fp32. Grid: (B*H, S/64). Block: 256 threads.
// Each block: 64 query rows, streams K/V in 64-row tiles, online softmax.
// Per-thread: 4x4 microtile of S and of O (16x16 thread grid).
// ----------------------------------------------------------------------------
#define FA_SMEM_FLOATS (4 * 64 * 68 + 3 * 64)
#define FA_SMEM_BYTES  (FA_SMEM_FLOATS * 4)

__global__ __launch_bounds__(256) void flash_attn(const float* __restrict__ mask)
{
    extern __shared__ float sm[];
    float* Qt    = sm;                 // [64 d][68]  (transposed: Qt[d][i])
    float* Kt    = Qt + 64 * 68;       // [64 d][68]  (Kt[d][j])
    float* Vs    = Kt + 64 * 68;       // [64 j][68]  (row-major)
    float* Ss    = Vs + 64 * 68;       // [64 i][68]  scores then probs
    float* row_m = Ss + 64 * 68;       // [64]
    float* row_l = row_m + 64;         // [64]
    float* row_a = row_l + 64;         // [64]

    const int tid = threadIdx.x;
    const int bh  = blockIdx.x;
    const int b   = bh / HEADS;
    const int h   = bh % HEADS;
    const int qb  = blockIdx.y;

    const float* Qg = g_q + ((size_t)(b * SEQ + qb * 64)) * D_MODEL + h * HEAD_DIM;
    const float* Kg = g_k + ((size_t)(b * SEQ)) * D_MODEL + h * HEAD_DIM;
    const float* Vg = g_v + ((size_t)(b * SEQ)) * D_MODEL + h * HEAD_DIM;
    const float* Mg = mask + ((size_t)b * SEQ + qb * 64) * SEQ;

    // Load Q tile transposed into Qt[d][i]
    #pragma unroll
    for (int l = 0; l < 4; l++) {
        int idx = tid + l * 256;       // 0..1023
        int r   = idx >> 4;            // query row 0..63
        int d4  = (idx & 15) * 4;      // 0..60
        float4 q = *(const float4*)(Qg + (size_t)r * D_MODEL + d4);
        Qt[(d4 + 0) * 68 + r] = q.x;
        Qt[(d4 + 1) * 68 + r] = q.y;
        Qt[(d4 + 2) * 68 + r] = q.z;
        Qt[(d4 + 3) * 68 + r] = q.w;
    }
    if (tid < 64) { row_m[tid] = -1e30f; row_l[tid] = 0.0f; }

    const int tm = tid >> 4;           // 0..15: query rows tm*4..+3
    const int tn = tid & 15;           // 0..15: cols tn*4..+3
    float o[4][4];
    #pragma unroll
    for (int i = 0; i < 4; i++)
        #pragma unroll
        for (int j = 0; j < 4; j++) o[i][j] = 0.0f;

    __syncthreads();

    for (int kb = 0; kb < SEQ / 64; kb++) {
        // Load K tile (transposed) and V tile (row-major)
        #pragma unroll
        for (int l = 0; l < 4; l++) {
            int idx = tid + l * 256;
            int r   = idx >> 4;
            int d4  = (idx & 15) * 4;
            float4 k = *(const float4*)(Kg + (size_t)(kb * 64 + r) * D_MODEL + d4);
            Kt[(d4 + 0) * 68 + r] = k.x;
            Kt[(d4 + 1) * 68 + r] = k.y;
            Kt[(d4 + 2) * 68 + r] = k.z;
            Kt[(d4 + 3) * 68 + r] = k.w;
            float4 v = *(const float4*)(Vg + (size_t)(kb * 64 + r) * D_MODEL + d4);
            *(float4*)&Vs[r * 68 + d4] = v;
        }
        __syncthreads();

        // S = (Q K^T) for this tile
        float s[4][4];
        #pragma unroll
        for (int i = 0; i < 4; i++)
            #pragma unroll
            for (int j = 0; j < 4; j++) s[i][j] = 0.0f;

        #pragma unroll 8
        for (int d = 0; d < 64; d++) {
            float4 qa = *(const float4*)&Qt[d * 68 + tm * 4];
            float4 ka = *(const float4*)&Kt[d * 68 + tn * 4];
            float aq[4] = {qa.x, qa.y, qa.z, qa.w};
            float bk[4] = {ka.x, ka.y, ka.z, ka.w};
            #pragma unroll
            for (int i = 0; i < 4; i++)
                #pragma unroll
                for (int j = 0; j < 4; j++)
                    s[i][j] = fmaf(aq[i], bk[j], s[i][j]);
        }

        // scale by 1/sqrt(64), add (1-mask)*-1e9 = (mask-1)*1e9, write to Ss
        #pragma unroll
        for (int i = 0; i < 4; i++) {
            int r = tm * 4 + i;
            float4 mk = *(const float4*)(Mg + (size_t)r * SEQ + kb * 64 + tn * 4);
            float4 out;
            out.x = fmaf(s[i][0], 0.125f, (mk.x - 1.0f) * 1e9f);
            out.y = fmaf(s[i][1], 0.125f, (mk.y - 1.0f) * 1e9f);
            out.z = fmaf(s[i][2], 0.125f, (mk.z - 1.0f) * 1e9f);
            out.w = fmaf(s[i][3], 0.125f, (mk.w - 1.0f) * 1e9f);
            *(float4*)&Ss[r * 68 + tn * 4] = out;
        }
        __syncthreads();

        // Online softmax row pass: 4 threads per row (cols split into 16s)
        {
            int r  = tid >> 2;
            int qd = tid & 3;
            float* srow = &Ss[r * 68 + qd * 16];
            float mx = -1e30f;
            #pragma unroll
            for (int c = 0; c < 16; c++) mx = fmaxf(mx, srow[c]);
            mx = fmaxf(mx, __shfl_xor_sync(0xffffffffu, mx, 1));
            mx = fmaxf(mx, __shfl_xor_sync(0xffffffffu, mx, 2));
            float m_old = row_m[r];
            float m_new = fmaxf(m_old, mx);
            float sum = 0.0f;
            #pragma unroll
            for (int c = 0; c < 16; c++) {
                float p = __expf(srow[c] - m_new);
                srow[c] = p;
                sum += p;
            }
            sum += __shfl_xor_sync(0xffffffffu, sum, 1);
            sum += __shfl_xor_sync(0xffffffffu, sum, 2);
            if (qd == 0) {
                float al = __expf(m_old - m_new);
                row_a[r] = al;
                row_l[r] = row_l[r] * al + sum;
                row_m[r] = m_new;
            }
        }
        __syncthreads();

        // Rescale O, then O += P @ V
        float al[4];
        #pragma unroll
        for (int i = 0; i < 4; i++) al[i] = row_a[tm * 4 + i];
        #pragma unroll
        for (int i = 0; i < 4; i++)
            #pragma unroll
            for (int j = 0; j < 4; j++) o[i][j] *= al[i];

        #pragma unroll 8
        for (int j = 0; j < 64; j++) {
            float4 vv = *(const float4*)&Vs[j * 68 + tn * 4];
            float p0 = Ss[(tm * 4 + 0) * 68 + j];
            float p1 = Ss[(tm * 4 + 1) * 68 + j];
            float p2 = Ss[(tm * 4 + 2) * 68 + j];
            float p3 = Ss[(tm * 4 + 3) * 68 + j];
            o[0][0] = fmaf(p0, vv.x, o[0][0]); o[0][1] = fmaf(p0, vv.y, o[0][1]);
            o[0][2] = fmaf(p0, vv.z, o[0][2]); o[0][3] = fmaf(p0, vv.w, o[0][3]);
            o[1][0] = fmaf(p1, vv.x, o[1][0]); o[1][1] = fmaf(p1, vv.y, o[1][1]);
            o[1][2] = fmaf(p1, vv.z, o[1][2]); o[1][3] = fmaf(p1, vv.w, o[1][3]);
            o[2][0] = fmaf(p2, vv.x, o[2][0]); o[2][1] = fmaf(p2, vv.y, o[2][1]);
            o[2][2] = fmaf(p2, vv.z, o[2][2]); o[2][3] = fmaf(p2, vv.w, o[2][3]);
            o[3][0] = fmaf(p3, vv.x, o[3][0]); o[3][1] = fmaf(p3, vv.y, o[3][1]);
            o[3][2] = fmaf(p3, vv.z, o[3][2]); o[3][3] = fmaf(p3, vv.w, o[3][3]);
        }
        __syncthreads();
    }

    // Normalize and write out (head-major concat layout: [B, S, H*HEAD])
    float* Og = g_attn + ((size_t)(b * SEQ + qb * 64)) * D_MODEL + h * HEAD_DIM;
    #pragma unroll
    for (int i = 0; i < 4; i++) {
        int r = tm * 4 + i;
        float inv = 1.0f / row_l[r];
        float4 ov;
        ov.x = o[i][0] * inv; ov.y = o[i][1] * inv;
        ov.z = o[i][2] * inv; ov.w = o[i][3] * inv;
        *(float4*)&Og[(size_t)r * D_MODEL + tn * 4] = ov;
    }
}

// ----------------------------------------------------------------------------
extern "C" void kernel_launch(void* const* d_in, const int* in_sizes, int n_in,
                              void* d_out, int out_size)
{
    const float* x    = (const float*)d_in[0];
    const float* y    = (const float*)d_in[1];
    const float* mask = (const float*)d_in[2];
    const float* Wq   = (const float*)d_in[3];
    const float* bq   = (const float*)d_in[4];
    const float* Wk   = (const float*)d_in[5];
    const float* bk   = (const float*)d_in[6];
    const float* Wv   = (const float*)d_in[7];
    const float* bv   = (const float*)d_in[8];
    const float* Wo   = (const float*)d_in[9];
    const float* bo   = (const float*)d_in[10];
    float* out = (float*)d_out;

    float *gq, *gk, *gv, *ga;
    cudaGetSymbolAddress((void**)&gq, g_q);
    cudaGetSymbolAddress((void**)&gk, g_k);
    cudaGetSymbolAddress((void**)&gv, g_v);
    cudaGetSymbolAddress((void**)&ga, g_attn);

    dim3 ggrid(D_MODEL / 128, M_TOTAL / 128);   // (8, 32)
    dim3 gblk(256);

    // Projections
    gemm_nt_bias<<<ggrid, gblk>>>(x, Wq, bq, gq);
    gemm_nt_bias<<<ggrid, gblk>>>(y, Wk, bk, gk);
    gemm_nt_bias<<<ggrid, gblk>>>(y, Wv, bv, gv);

    // Attention
    cudaFuncSetAttribute(flash_attn, cudaFuncAttributeMaxDynamicSharedMemorySize,
                         FA_SMEM_BYTES);
    dim3 agrid(BATCH * HEADS, SEQ / 64);        // (32, 32)
    flash_attn<<<agrid, 256, FA_SMEM_BYTES>>>(mask);

    // Output projection
    gemm_nt_bias<<<ggrid, gblk>>>(ga, Wo, bo, out);
}

// round 3
// speedup vs baseline: 1.3333x; 1.3333x over previous
#include <cuda_runtime.h>
#include <cuda_bf16.h>
#include <cstdint>
#include <math.h>

// Problem constants (fixed by the dataset)
#define D_MODEL   1024
#define HEADS     16
#define HEAD_DIM  64
#define BATCH     2
#define SEQ       2048
#define M_TOTAL   (BATCH * SEQ)       // 4096 rows for projection GEMMs

// Scratch: device globals (no allocations allowed)
__device__ float g_q[M_TOTAL * D_MODEL];
__device__ float g_k[M_TOTAL * D_MODEL];
__device__ float g_v[M_TOTAL * D_MODEL];
__device__ float g_attn[M_TOTAL * D_MODEL];

// ============================================================================
// Warp-level MMA helpers (mma.sync + ldmatrix — supported on base sm_103)
// ============================================================================
__device__ __forceinline__ uint32_t smem_u32(const void* p) {
    uint32_t a;
    asm("{ .reg .u64 t; cvta.to.shared.u64 t, %1; cvt.u32.u64 %0, t; }"
        : "=r"(a) : "l"(p));
    return a;
}

__device__ __forceinline__ void ldm_x4(uint32_t* r, uint32_t addr) {
    asm volatile("ldmatrix.sync.aligned.m8n8.x4.shared.b16 {%0,%1,%2,%3}, [%4];"
                 : "=r"(r[0]), "=r"(r[1]), "=r"(r[2]), "=r"(r[3]) : "r"(addr));
}

// D += A(16x16) * B(16x8)  bf16 inputs, fp32 accum
__device__ __forceinline__ void mma16816(float* d, const uint32_t* a, const uint32_t* b) {
    asm volatile(
        "mma.sync.aligned.m16n8k16.row.col.f32.bf16.bf16.f32 "
        "{%0,%1,%2,%3}, {%4,%5,%6,%7}, {%8,%9}, {%0,%1,%2,%3};"
        : "+f"(d[0]), "+f"(d[1]), "+f"(d[2]), "+f"(d[3])
        : "r"(a[0]), "r"(a[1]), "r"(a[2]), "r"(a[3]), "r"(b[0]), "r"(b[1]));
}

// Convert 4 fp32 -> 4 bf16 hi + 4 bf16 lo (residual), store 8B to each tile
__device__ __forceinline__ void cvt_split_store(char* hi_tile, char* lo_tile,
                                                uint32_t off, float4 v) {
    uint32_t h01, h23, l01, l23;
    asm("cvt.rn.bf16x2.f32 %0, %1, %2;" : "=r"(h01) : "f"(v.y), "f"(v.x));
    asm("cvt.rn.bf16x2.f32 %0, %1, %2;" : "=r"(h23) : "f"(v.w), "f"(v.z));
    float r0 = v.x - __uint_as_float(h01 << 16);
    float r1 = v.y - __uint_as_float(h01 & 0xFFFF0000u);
    float r2 = v.z - __uint_as_float(h23 << 16);
    float r3 = v.w - __uint_as_float(h23 & 0xFFFF0000u);
    asm("cvt.rn.bf16x2.f32 %0, %1, %2;" : "=r"(l01) : "f"(r1), "f"(r0));
    asm("cvt.rn.bf16x2.f32 %0, %1, %2;" : "=r"(l23) : "f"(r3), "f"(r2));
    *(uint2*)(hi_tile + off) = make_uint2(h01, h23);
    *(uint2*)(lo_tile + off) = make_uint2(l01, l23);
}

// ============================================================================
// GEMM: C[M,N] = A[M,K] @ W[N,K]^T + bias   (M=4096, N=K=1024)
// CTA 128x128, BK=32, 8 warps (warp tile 32x64), bf16 hi/lo 3-pass split.
// SMEM tiles padded to 80B rows (40 halves) -> conflict-free ldmatrix.
// ============================================================================
#define BM 128
#define BN 128
#define BK 32
#define KITERS (D_MODEL / BK)       // 32
#define LDT 40                       // tile row stride in halves (80 bytes)
#define TILE_BYTES (128 * LDT * 2)   // 10240

__global__ __launch_bounds__(256) void gemm_mma(
    const float* __restrict__ A,
    const float* __restrict__ W,
    const float* __restrict__ bias,
    float* __restrict__ C)
{
    __shared__ char sm[4 * TILE_BYTES];   // As_hi, As_lo, Bs_hi, Bs_lo
    char* As_hi = sm;
    char* As_lo = sm + TILE_BYTES;
    char* Bs_hi = sm + 2 * TILE_BYTES;
    char* Bs_lo = sm + 3 * TILE_BYTES;

    const int tid    = threadIdx.x;
    const int lane   = tid & 31;
    const int wid    = tid >> 5;
    const int warp_m = wid & 3;          // 4 warps along M (32 rows each)
    const int warp_n = wid >> 2;         // 2 warps along N (64 cols each)
    const int bm     = blockIdx.y;
    const int bn     = blockIdx.x;

    const float* Ag = A + (size_t)bm * BM * D_MODEL;
    const float* Wg = W + (size_t)bn * BN * D_MODEL;

    // Global->smem mapping: f = tid + i*256; row = f>>3 (0..127); c4 = (f&7)*4
    uint32_t st_off[4];
    uint32_t gl_off[4];
    #pragma unroll
    for (int i = 0; i < 4; i++) {
        int f = tid + i * 256;
        int r = f >> 3, c4 = (f & 7) * 4;
        st_off[i] = (uint32_t)(r * (LDT * 2) + c4 * 2);
        gl_off[i] = (uint32_t)(r * D_MODEL + c4);
    }

    // ldmatrix per-thread byte offsets (within a tile)
    const uint32_t a_base = smem_u32(As_hi);
    // A .x4: row = warp_m*32 + (lane%8) + ((lane>>3)&1)*8, col = (lane>>4)*8
    const uint32_t a_off =
        (uint32_t)((warp_m * 32 + (lane & 7) + ((lane >> 3) & 1) * 8) * (LDT * 2)
                   + (lane >> 4) * 16);
    // B .x4: row n = warp_n*64 + (lane%8), col = (lane>>3)*8  (covers k0..31)
    const uint32_t b_off =
        (uint32_t)((warp_n * 64 + (lane & 7)) * (LDT * 2) + (lane >> 3) * 16);

    float acc[2][8][4];
    #pragma unroll
    for (int mt = 0; mt < 2; mt++)
        #pragma unroll
        for (int nt = 0; nt < 8; nt++)
            #pragma unroll
            for (int j = 0; j < 4; j++) acc[mt][nt][j] = 0.0f;

    // Prefetch k-tile 0
    float4 pa[4], pb[4];
    #pragma unroll
    for (int i = 0; i < 4; i++) {
        pa[i] = *(const float4*)(Ag + gl_off[i]);
        pb[i] = *(const float4*)(Wg + gl_off[i]);
    }

    for (int it = 0; it < KITERS; it++) {
        // Store current tile (hi/lo split)
        #pragma unroll
        for (int i = 0; i < 4; i++) {
            cvt_split_store(As_hi, As_lo, st_off[i], pa[i]);
            cvt_split_store(Bs_hi, Bs_lo, st_off[i], pb[i]);
        }
        __syncthreads();

        // Prefetch next tile (overlaps with MMA work below)
        if (it + 1 < KITERS) {
            const uint32_t g = (uint32_t)((it + 1) * BK);
            #pragma unroll
            for (int i = 0; i < 4; i++) {
                pa[i] = *(const float4*)(Ag + gl_off[i] + g);
                pb[i] = *(const float4*)(Wg + gl_off[i] + g);
            }
        }

        // Load A fragments: [ks][mt] hi and lo
        uint32_t ah[2][2][4], al[2][2][4];
        #pragma unroll
        for (int ks = 0; ks < 2; ks++)
            #pragma unroll
            for (int mt = 0; mt < 2; mt++) {
                uint32_t off = a_off + (uint32_t)(mt * 16 * (LDT * 2) + ks * 32);
                ldm_x4(ah[ks][mt], a_base + off);
                ldm_x4(al[ks][mt], a_base + TILE_BYTES + off);
            }

        // Per n-tile: load B frags (both k-steps) and issue 12 MMAs
        #pragma unroll
        for (int nt = 0; nt < 8; nt++) {
            uint32_t off = b_off + (uint32_t)(nt * 8 * (LDT * 2));
            uint32_t bh[4], bl[4];     // [0..1]=ks0, [2..3]=ks1
            ldm_x4(bh, a_base + 2 * TILE_BYTES + off);
            ldm_x4(bl, a_base + 3 * TILE_BYTES + off);
            #pragma unroll
            for (int ks = 0; ks < 2; ks++)
                #pragma unroll
                for (int mt = 0; mt < 2; mt++) {
                    mma16816(acc[mt][nt], ah[ks][mt], bh + ks * 2);
                    mma16816(acc[mt][nt], ah[ks][mt], bl + ks * 2);
                    mma16816(acc[mt][nt], al[ks][mt], bh + ks * 2);
                }
        }
        __syncthreads();
    }

    // Epilogue: C layout per mma frag; add bias, float2 stores
    const int lrow = lane >> 2;
    const int lcol = (lane & 3) * 2;
    #pragma unroll
    for (int mt = 0; mt < 2; mt++) {
        const int r0 = bm * BM + warp_m * 32 + mt * 16 + lrow;
        #pragma unroll
        for (int nt = 0; nt < 8; nt++) {
            const int cg = bn * BN + warp_n * 64 + nt * 8 + lcol;
            const float b0 = bias[cg], b1 = bias[cg + 1];
            float2 v0 = make_float2(acc[mt][nt][0] + b0, acc[mt][nt][1] + b1);
            float2 v1 = make_float2(acc[mt][nt][2] + b0, acc[mt][nt][3] + b1);
            *(float2*)(C + (size_t)r0 * D_MODEL + cg)       = v0;
            *(float2*)(C + (size_t)(r0 + 8) * D_MODEL + cg) = v1;
        }
    }
}

// ----------------------------------------------------------------------------
// Flash attention, fp32 (unchanged — known good). Grid: (B*H, S/64), 256 thr.
// ----------------------------------------------------------------------------
#define FA_SMEM_FLOATS (4 * 64 * 68 + 3 * 64)
#define FA_SMEM_BYTES  (FA_SMEM_FLOATS * 4)

__global__ __launch_bounds__(256) void flash_attn(const float* __restrict__ mask)
{
    extern __shared__ float smf[];
    float* Qt    = smf;
    float* Kt    = Qt + 64 * 68;
    float* Vs    = Kt + 64 * 68;
    float* Ss    = Vs + 64 * 68;
    float* row_m = Ss + 64 * 68;
    float* row_l = row_m + 64;
    float* row_a = row_l + 64;

    const int tid = threadIdx.x;
    const int bh  = blockIdx.x;
    const int b   = bh / HEADS;
    const int h   = bh % HEADS;
    const int qb  = blockIdx.y;

    const float* Qg = g_q + ((size_t)(b * SEQ + qb * 64)) * D_MODEL + h * HEAD_DIM;
    const float* Kg = g_k + ((size_t)(b * SEQ)) * D_MODEL + h * HEAD_DIM;
    const float* Vg = g_v + ((size_t)(b * SEQ)) * D_MODEL + h * HEAD_DIM;
    const float* Mg = mask + ((size_t)b * SEQ + qb * 64) * SEQ;

    #pragma unroll
    for (int l = 0; l < 4; l++) {
        int idx = tid + l * 256;
        int r   = idx >> 4;
        int d4  = (idx & 15) * 4;
        float4 q = *(const float4*)(Qg + (size_t)r * D_MODEL + d4);
        Qt[(d4 + 0) * 68 + r] = q.x;
        Qt[(d4 + 1) * 68 + r] = q.y;
        Qt[(d4 + 2) * 68 + r] = q.z;
        Qt[(d4 + 3) * 68 + r] = q.w;
    }
    if (tid < 64) { row_m[tid] = -1e30f; row_l[tid] = 0.0f; }

    const int tm = tid >> 4;
    const int tn = tid & 15;
    float o[4][4];
    #pragma unroll
    for (int i = 0; i < 4; i++)
        #pragma unroll
        for (int j = 0; j < 4; j++) o[i][j] = 0.0f;

    __syncthreads();

    for (int kb = 0; kb < SEQ / 64; kb++) {
        #pragma unroll
        for (int l = 0; l < 4; l++) {
            int idx = tid + l * 256;
            int r   = idx >> 4;
            int d4  = (idx & 15) * 4;
            float4 k = *(const float4*)(Kg + (size_t)(kb * 64 + r) * D_MODEL + d4);
            Kt[(d4 + 0) * 68 + r] = k.x;
            Kt[(d4 + 1) * 68 + r] = k.y;
            Kt[(d4 + 2) * 68 + r] = k.z;
            Kt[(d4 + 3) * 68 + r] = k.w;
            float4 v = *(const float4*)(Vg + (size_t)(kb * 64 + r) * D_MODEL + d4);
            *(float4*)&Vs[r * 68 + d4] = v;
        }
        __syncthreads();

        float s[4][4];
        #pragma unroll
        for (int i = 0; i < 4; i++)
            #pragma unroll
            for (int j = 0; j < 4; j++) s[i][j] = 0.0f;

        #pragma unroll 8
        for (int d = 0; d < 64; d++) {
            float4 qa = *(const float4*)&Qt[d * 68 + tm * 4];
            float4 ka = *(const float4*)&Kt[d * 68 + tn * 4];
            float aq[4] = {qa.x, qa.y, qa.z, qa.w};
            float bk[4] = {ka.x, ka.y, ka.z, ka.w};
            #pragma unroll
            for (int i = 0; i < 4; i++)
                #pragma unroll
                for (int j = 0; j < 4; j++)
                    s[i][j] = fmaf(aq[i], bk[j], s[i][j]);
        }

        #pragma unroll
        for (int i = 0; i < 4; i++) {
            int r = tm * 4 + i;
            float4 mk = *(const float4*)(Mg + (size_t)r * SEQ + kb * 64 + tn * 4);
            float4 out;
            out.x = fmaf(s[i][0], 0.125f, (mk.x - 1.0f) * 1e9f);
            out.y = fmaf(s[i][1], 0.125f, (mk.y - 1.0f) * 1e9f);
            out.z = fmaf(s[i][2], 0.125f, (mk.z - 1.0f) * 1e9f);
            out.w = fmaf(s[i][3], 0.125f, (mk.w - 1.0f) * 1e9f);
            *(float4*)&Ss[r * 68 + tn * 4] = out;
        }
        __syncthreads();

        {
            int r  = tid >> 2;
            int qd = tid & 3;
            float* srow = &Ss[r * 68 + qd * 16];
            float mx = -1e30f;
            #pragma unroll
            for (int c = 0; c < 16; c++) mx = fmaxf(mx, srow[c]);
            mx = fmaxf(mx, __shfl_xor_sync(0xffffffffu, mx, 1));
            mx = fmaxf(mx, __shfl_xor_sync(0xffffffffu, mx, 2));
            float m_old = row_m[r];
            float m_new = fmaxf(m_old, mx);
            float sum = 0.0f;
            #pragma unroll
            for (int c = 0; c < 16; c++) {
                float p = __expf(srow[c] - m_new);
                srow[c] = p;
                sum += p;
            }
            sum += __shfl_xor_sync(0xffffffffu, sum, 1);
            sum += __shfl_xor_sync(0xffffffffu, sum, 2);
            if (qd == 0) {
                float al = __expf(m_old - m_new);
                row_a[r] = al;
                row_l[r] = row_l[r] * al + sum;
                row_m[r] = m_new;
            }
        }
        __syncthreads();

        float al[4];
        #pragma unroll
        for (int i = 0; i < 4; i++) al[i] = row_a[tm * 4 + i];
        #pragma unroll
        for (int i = 0; i < 4; i++)
            #pragma unroll
            for (int j = 0; j < 4; j++) o[i][j] *= al[i];

        #pragma unroll 8
        for (int j = 0; j < 64; j++) {
            float4 vv = *(const float4*)&Vs[j * 68 + tn * 4];
            float p0 = Ss[(tm * 4 + 0) * 68 + j];
            float p1 = Ss[(tm * 4 + 1) * 68 + j];
            float p2 = Ss[(tm * 4 + 2) * 68 + j];
            float p3 = Ss[(tm * 4 + 3) * 68 + j];
            o[0][0] = fmaf(p0, vv.x, o[0][0]); o[0][1] = fmaf(p0, vv.y, o[0][1]);
            o[0][2] = fmaf(p0, vv.z, o[0][2]); o[0][3] = fmaf(p0, vv.w, o[0][3]);
            o[1][0] = fmaf(p1, vv.x, o[1][0]); o[1][1] = fmaf(p1, vv.y, o[1][1]);
            o[1][2] = fmaf(p1, vv.z, o[1][2]); o[1][3] = fmaf(p1, vv.w, o[1][3]);
            o[2][0] = fmaf(p2, vv.x, o[2][0]); o[2][1] = fmaf(p2, vv.y, o[2][1]);
            o[2][2] = fmaf(p2, vv.z, o[2][2]); o[2][3] = fmaf(p2, vv.w, o[2][3]);
            o[3][0] = fmaf(p3, vv.x, o[3][0]); o[3][1] = fmaf(p3, vv.y, o[3][1]);
            o[3][2] = fmaf(p3, vv.z, o[3][2]); o[3][3] = fmaf(p3, vv.w, o[3][3]);
        }
        __syncthreads();
    }

    float* Og = g_attn + ((size_t)(b * SEQ + qb * 64)) * D_MODEL + h * HEAD_DIM;
    #pragma unroll
    for (int i = 0; i < 4; i++) {
        int r = tm * 4 + i;
        float inv = 1.0f / row_l[r];
        float4 ov;
        ov.x = o[i][0] * inv; ov.y = o[i][1] * inv;
        ov.z = o[i][2] * inv; ov.w = o[i][3] * inv;
        *(float4*)&Og[(size_t)r * D_MODEL + tn * 4] = ov;
    }
}

// ----------------------------------------------------------------------------
extern "C" void kernel_launch(void* const* d_in, const int* in_sizes, int n_in,
                              void* d_out, int out_size)
{
    const float* x    = (const float*)d_in[0];
    const float* y    = (const float*)d_in[1];
    const float* mask = (const float*)d_in[2];
    const float* Wq   = (const float*)d_in[3];
    const float* bq   = (const float*)d_in[4];
    const float* Wk   = (const float*)d_in[5];
    const float* bk   = (const float*)d_in[6];
    const float* Wv   = (const float*)d_in[7];
    const float* bv   = (const float*)d_in[8];
    const float* Wo   = (const float*)d_in[9];
    const float* bo   = (const float*)d_in[10];
    float* out = (float*)d_out;

    float *gq, *gk, *gv, *ga;
    cudaGetSymbolAddress((void**)&gq, g_q);
    cudaGetSymbolAddress((void**)&gk, g_k);
    cudaGetSymbolAddress((void**)&gv, g_v);
    cudaGetSymbolAddress((void**)&ga, g_attn);

    cudaFuncSetAttribute(flash_attn, cudaFuncAttributeMaxDynamicSharedMemorySize,
                         FA_SMEM_BYTES);

    dim3 ggrid(D_MODEL / BN, M_TOTAL / BM);     // (8, 32)
    gemm_mma<<<ggrid, 256>>>(x, Wq, bq, gq);
    gemm_mma<<<ggrid, 256>>>(y, Wk, bk, gk);
    gemm_mma<<<ggrid, 256>>>(y, Wv, bv, gv);

    dim3 agrid(BATCH * HEADS, SEQ / 64);        // (32, 32)
    flash_attn<<<agrid, 256, FA_SMEM_BYTES>>>(mask);

    gemm_mma<<<ggrid, 256>>>(ga, Wo, bo, out);
}

// round 5
// speedup vs baseline: 1.3358x; 1.0018x over previous
#include <cuda_runtime.h>
#include <cuda_bf16.h>
#include <cstdint>
#include <math.h>

// Problem constants (fixed by the dataset)
#define D_MODEL   1024
#define HEADS     16
#define HEAD_DIM  64
#define BATCH     2
#define SEQ       2048
#define M_TOTAL   (BATCH * SEQ)       // 4096 rows for projection GEMMs

// Scratch: device globals (no allocations allowed)
__device__ float g_q[M_TOTAL * D_MODEL];
__device__ float g_k[M_TOTAL * D_MODEL];
__device__ float g_v[M_TOTAL * D_MODEL];
__device__ float g_attn[M_TOTAL * D_MODEL];

// ============================================================================
// Warp-level MMA helpers (mma.sync + ldmatrix — supported on base sm_103)
// ============================================================================
__device__ __forceinline__ uint32_t smem_u32(const void* p) {
    uint32_t a;
    asm("{ .reg .u64 t; cvta.to.shared.u64 t, %1; cvt.u32.u64 %0, t; }"
        : "=r"(a) : "l"(p));
    return a;
}

__device__ __forceinline__ void ldm_x4(uint32_t* r, uint32_t addr) {
    asm volatile("ldmatrix.sync.aligned.m8n8.x4.shared.b16 {%0,%1,%2,%3}, [%4];"
                 : "=r"(r[0]), "=r"(r[1]), "=r"(r[2]), "=r"(r[3]) : "r"(addr));
}

// D += A(16x16) * B(16x8)  bf16 inputs, fp32 accum
__device__ __forceinline__ void mma16816(float* d, const uint32_t* a, const uint32_t* b) {
    asm volatile(
        "mma.sync.aligned.m16n8k16.row.col.f32.bf16.bf16.f32 "
        "{%0,%1,%2,%3}, {%4,%5,%6,%7}, {%8,%9}, {%0,%1,%2,%3};"
        : "+f"(d[0]), "+f"(d[1]), "+f"(d[2]), "+f"(d[3])
        : "r"(a[0]), "r"(a[1]), "r"(a[2]), "r"(a[3]), "r"(b[0]), "r"(b[1]));
}

// Convert 4 fp32 -> 4 bf16 hi + 4 bf16 lo (residual), store 8B to each tile
__device__ __forceinline__ void cvt_split_store(char* hi_tile, char* lo_tile,
                                                uint32_t off, float4 v) {
    uint32_t h01, h23, l01, l23;
    asm("cvt.rn.bf16x2.f32 %0, %1, %2;" : "=r"(h01) : "f"(v.y), "f"(v.x));
    asm("cvt.rn.bf16x2.f32 %0, %1, %2;" : "=r"(h23) : "f"(v.w), "f"(v.z));
    float r0 = v.x - __uint_as_float(h01 << 16);
    float r1 = v.y - __uint_as_float(h01 & 0xFFFF0000u);
    float r2 = v.z - __uint_as_float(h23 << 16);
    float r3 = v.w - __uint_as_float(h23 & 0xFFFF0000u);
    asm("cvt.rn.bf16x2.f32 %0, %1, %2;" : "=r"(l01) : "f"(r1), "f"(r0));
    asm("cvt.rn.bf16x2.f32 %0, %1, %2;" : "=r"(l23) : "f"(r3), "f"(r2));
    *(uint2*)(hi_tile + off) = make_uint2(h01, h23);
    *(uint2*)(lo_tile + off) = make_uint2(l01, l23);
}

// ============================================================================
// GEMM: C[M,N] = A[M,K] @ W[N,K]^T + bias   (M=4096, N=K=1024)
// CTA 128x128, BK=32, 8 warps (warp tile 32x64), bf16 hi/lo 3-pass split.
// SMEM tiles padded to 80B rows (40 halves) -> conflict-free ldmatrix.
// ============================================================================
#define BM 128
#define BN 128
#define BK 32
#define KITERS (D_MODEL / BK)       // 32
#define LDT 40                       // tile row stride in halves (80 bytes)
#define TILE_BYTES (128 * LDT * 2)   // 10240

__global__ __launch_bounds__(256) void gemm_mma(
    const float* __restrict__ A,
    const float* __restrict__ W,
    const float* __restrict__ bias,
    float* __restrict__ C)
{
    __shared__ char sm[4 * TILE_BYTES];   // As_hi, As_lo, Bs_hi, Bs_lo
    char* As_hi = sm;
    char* As_lo = sm + TILE_BYTES;
    char* Bs_hi = sm + 2 * TILE_BYTES;
    char* Bs_lo = sm + 3 * TILE_BYTES;

    const int tid    = threadIdx.x;
    const int lane   = tid & 31;
    const int wid    = tid >> 5;
    const int warp_m = wid & 3;          // 4 warps along M (32 rows each)
    const int warp_n = wid >> 2;         // 2 warps along N (64 cols each)
    const int bm     = blockIdx.y;
    const int bn     = blockIdx.x;

    const float* Ag = A + (size_t)bm * BM * D_MODEL;
    const float* Wg = W + (size_t)bn * BN * D_MODEL;

    // Global->smem mapping: f = tid + i*256; row = f>>3 (0..127); c4 = (f&7)*4
    uint32_t st_off[4];
    uint32_t gl_off[4];
    #pragma unroll
    for (int i = 0; i < 4; i++) {
        int f = tid + i * 256;
        int r = f >> 3, c4 = (f & 7) * 4;
        st_off[i] = (uint32_t)(r * (LDT * 2) + c4 * 2);
        gl_off[i] = (uint32_t)(r * D_MODEL + c4);
    }

    // ldmatrix per-thread byte offsets (within a tile)
    const uint32_t a_base = smem_u32(As_hi);
    // A .x4: row = warp_m*32 + (lane%8) + ((lane>>3)&1)*8, col = (lane>>4)*8
    const uint32_t a_off =
        (uint32_t)((warp_m * 32 + (lane & 7) + ((lane >> 3) & 1) * 8) * (LDT * 2)
                   + (lane >> 4) * 16);
    // B .x4: row n = warp_n*64 + (lane%8), col = (lane>>3)*8  (covers k0..31)
    const uint32_t b_off =
        (uint32_t)((warp_n * 64 + (lane & 7)) * (LDT * 2) + (lane >> 3) * 16);

    float acc[2][8][4];
    #pragma unroll
    for (int mt = 0; mt < 2; mt++)
        #pragma unroll
        for (int nt = 0; nt < 8; nt++)
            #pragma unroll
            for (int j = 0; j < 4; j++) acc[mt][nt][j] = 0.0f;

    // Prefetch k-tile 0
    float4 pa[4], pb[4];
    #pragma unroll
    for (int i = 0; i < 4; i++) {
        pa[i] = *(const float4*)(Ag + gl_off[i]);
        pb[i] = *(const float4*)(Wg + gl_off[i]);
    }

    for (int it = 0; it < KITERS; it++) {
        // Store current tile (hi/lo split)
        #pragma unroll
        for (int i = 0; i < 4; i++) {
            cvt_split_store(As_hi, As_lo, st_off[i], pa[i]);
            cvt_split_store(Bs_hi, Bs_lo, st_off[i], pb[i]);
        }
        __syncthreads();

        // Prefetch next tile (overlaps with MMA work below)
        if (it + 1 < KITERS) {
            const uint32_t g = (uint32_t)((it + 1) * BK);
            #pragma unroll
            for (int i = 0; i < 4; i++) {
                pa[i] = *(const float4*)(Ag + gl_off[i] + g);
                pb[i] = *(const float4*)(Wg + gl_off[i] + g);
            }
        }

        // Load A fragments: [ks][mt] hi and lo
        uint32_t ah[2][2][4], al[2][2][4];
        #pragma unroll
        for (int ks = 0; ks < 2; ks++)
            #pragma unroll
            for (int mt = 0; mt < 2; mt++) {
                uint32_t off = a_off + (uint32_t)(mt * 16 * (LDT * 2) + ks * 32);
                ldm_x4(ah[ks][mt], a_base + off);
                ldm_x4(al[ks][mt], a_base + TILE_BYTES + off);
            }

        // Per n-tile: load B frags (both k-steps) and issue 12 MMAs
        #pragma unroll
        for (int nt = 0; nt < 8; nt++) {
            uint32_t off = b_off + (uint32_t)(nt * 8 * (LDT * 2));
            uint32_t bh[4], bl[4];     // [0..1]=ks0, [2..3]=ks1
            ldm_x4(bh, a_base + 2 * TILE_BYTES + off);
            ldm_x4(bl, a_base + 3 * TILE_BYTES + off);
            #pragma unroll
            for (int ks = 0; ks < 2; ks++)
                #pragma unroll
                for (int mt = 0; mt < 2; mt++) {
                    mma16816(acc[mt][nt], ah[ks][mt], bh + ks * 2);
                    mma16816(acc[mt][nt], ah[ks][mt], bl + ks * 2);
                    mma16816(acc[mt][nt], al[ks][mt], bh + ks * 2);
                }
        }
        __syncthreads();
    }

    // Epilogue: C layout per mma frag; add bias, float2 stores
    const int lrow = lane >> 2;
    const int lcol = (lane & 3) * 2;
    #pragma unroll
    for (int mt = 0; mt < 2; mt++) {
        const int r0 = bm * BM + warp_m * 32 + mt * 16 + lrow;
        #pragma unroll
        for (int nt = 0; nt < 8; nt++) {
            const int cg = bn * BN + warp_n * 64 + nt * 8 + lcol;
            const float b0 = bias[cg], b1 = bias[cg + 1];
            float2 v0 = make_float2(acc[mt][nt][0] + b0, acc[mt][nt][1] + b1);
            float2 v1 = make_float2(acc[mt][nt][2] + b0, acc[mt][nt][3] + b1);
            *(float2*)(C + (size_t)r0 * D_MODEL + cg)       = v0;
            *(float2*)(C + (size_t)(r0 + 8) * D_MODEL + cg) = v1;
        }
    }
}

// ----------------------------------------------------------------------------
// Flash attention, fp32 (unchanged — known good). Grid: (B*H, S/64), 256 thr.
// ----------------------------------------------------------------------------
#define FA_SMEM_FLOATS (4 * 64 * 68 + 3 * 64)
#define FA_SMEM_BYTES  (FA_SMEM_FLOATS * 4)

__global__ __launch_bounds__(256) void flash_attn(const float* __restrict__ mask)
{
    extern __shared__ float smf[];
    float* Qt    = smf;
    float* Kt    = Qt + 64 * 68;
    float* Vs    = Kt + 64 * 68;
    float* Ss    = Vs + 64 * 68;
    float* row_m = Ss + 64 * 68;
    float* row_l = row_m + 64;
    float* row_a = row_l + 64;

    const int tid = threadIdx.x;
    const int bh  = blockIdx.x;
    const int b   = bh / HEADS;
    const int h   = bh % HEADS;
    const int qb  = blockIdx.y;

    const float* Qg = g_q + ((size_t)(b * SEQ + qb * 64)) * D_MODEL + h * HEAD_DIM;
    const float* Kg = g_k + ((size_t)(b * SEQ)) * D_MODEL + h * HEAD_DIM;
    const float* Vg = g_v + ((size_t)(b * SEQ)) * D_MODEL + h * HEAD_DIM;
    const float* Mg = mask + ((size_t)b * SEQ + qb * 64) * SEQ;

    #pragma unroll
    for (int l = 0; l < 4; l++) {
        int idx = tid + l * 256;
        int r   = idx >> 4;
        int d4  = (idx & 15) * 4;
        float4 q = *(const float4*)(Qg + (size_t)r * D_MODEL + d4);
        Qt[(d4 + 0) * 68 + r] = q.x;
        Qt[(d4 + 1) * 68 + r] = q.y;
        Qt[(d4 + 2) * 68 + r] = q.z;
        Qt[(d4 + 3) * 68 + r] = q.w;
    }
    if (tid < 64) { row_m[tid] = -1e30f; row_l[tid] = 0.0f; }

    const int tm = tid >> 4;
    const int tn = tid & 15;
    float o[4][4];
    #pragma unroll
    for (int i = 0; i < 4; i++)
        #pragma unroll
        for (int j = 0; j < 4; j++) o[i][j] = 0.0f;

    __syncthreads();

    for (int kb = 0; kb < SEQ / 64; kb++) {
        #pragma unroll
        for (int l = 0; l < 4; l++) {
            int idx = tid + l * 256;
            int r   = idx >> 4;
            int d4  = (idx & 15) * 4;
            float4 k = *(const float4*)(Kg + (size_t)(kb * 64 + r) * D_MODEL + d4);
            Kt[(d4 + 0) * 68 + r] = k.x;
            Kt[(d4 + 1) * 68 + r] = k.y;
            Kt[(d4 + 2) * 68 + r] = k.z;
            Kt[(d4 + 3) * 68 + r] = k.w;
            float4 v = *(const float4*)(Vg + (size_t)(kb * 64 + r) * D_MODEL + d4);
            *(float4*)&Vs[r * 68 + d4] = v;
        }
        __syncthreads();

        float s[4][4];
        #pragma unroll
        for (int i = 0; i < 4; i++)
            #pragma unroll
            for (int j = 0; j < 4; j++) s[i][j] = 0.0f;

        #pragma unroll 8
        for (int d = 0; d < 64; d++) {
            float4 qa = *(const float4*)&Qt[d * 68 + tm * 4];
            float4 ka = *(const float4*)&Kt[d * 68 + tn * 4];
            float aq[4] = {qa.x, qa.y, qa.z, qa.w};
            float bk[4] = {ka.x, ka.y, ka.z, ka.w};
            #pragma unroll
            for (int i = 0; i < 4; i++)
                #pragma unroll
                for (int j = 0; j < 4; j++)
                    s[i][j] = fmaf(aq[i], bk[j], s[i][j]);
        }

        #pragma unroll
        for (int i = 0; i < 4; i++) {
            int r = tm * 4 + i;
            float4 mk = *(const float4*)(Mg + (size_t)r * SEQ + kb * 64 + tn * 4);
            float4 out;
            out.x = fmaf(s[i][0], 0.125f, (mk.x - 1.0f) * 1e9f);
            out.y = fmaf(s[i][1], 0.125f, (mk.y - 1.0f) * 1e9f);
            out.z = fmaf(s[i][2], 0.125f, (mk.z - 1.0f) * 1e9f);
            out.w = fmaf(s[i][3], 0.125f, (mk.w - 1.0f) * 1e9f);
            *(float4*)&Ss[r * 68 + tn * 4] = out;
        }
        __syncthreads();

        {
            int r  = tid >> 2;
            int qd = tid & 3;
            float* srow = &Ss[r * 68 + qd * 16];
            float mx = -1e30f;
            #pragma unroll
            for (int c = 0; c < 16; c++) mx = fmaxf(mx, srow[c]);
            mx = fmaxf(mx, __shfl_xor_sync(0xffffffffu, mx, 1));
            mx = fmaxf(mx, __shfl_xor_sync(0xffffffffu, mx, 2));
            float m_old = row_m[r];
            float m_new = fmaxf(m_old, mx);
            float sum = 0.0f;
            #pragma unroll
            for (int c = 0; c < 16; c++) {
                float p = __expf(srow[c] - m_new);
                srow[c] = p;
                sum += p;
            }
            sum += __shfl_xor_sync(0xffffffffu, sum, 1);
            sum += __shfl_xor_sync(0xffffffffu, sum, 2);
            if (qd == 0) {
                float al = __expf(m_old - m_new);
                row_a[r] = al;
                row_l[r] = row_l[r] * al + sum;
                row_m[r] = m_new;
            }
        }
        __syncthreads();

        float al[4];
        #pragma unroll
        for (int i = 0; i < 4; i++) al[i] = row_a[tm * 4 + i];
        #pragma unroll
        for (int i = 0; i < 4; i++)
            #pragma unroll
            for (int j = 0; j < 4; j++) o[i][j] *= al[i];

        #pragma unroll 8
        for (int j = 0; j < 64; j++) {
            float4 vv = *(const float4*)&Vs[j * 68 + tn * 4];
            float p0 = Ss[(tm * 4 + 0) * 68 + j];
            float p1 = Ss[(tm * 4 + 1) * 68 + j];
            float p2 = Ss[(tm * 4 + 2) * 68 + j];
            float p3 = Ss[(tm * 4 + 3) * 68 + j];
            o[0][0] = fmaf(p0, vv.x, o[0][0]); o[0][1] = fmaf(p0, vv.y, o[0][1]);
            o[0][2] = fmaf(p0, vv.z, o[0][2]); o[0][3] = fmaf(p0, vv.w, o[0][3]);
            o[1][0] = fmaf(p1, vv.x, o[1][0]); o[1][1] = fmaf(p1, vv.y, o[1][1]);
            o[1][2] = fmaf(p1, vv.z, o[1][2]); o[1][3] = fmaf(p1, vv.w, o[1][3]);
            o[2][0] = fmaf(p2, vv.x, o[2][0]); o[2][1] = fmaf(p2, vv.y, o[2][1]);
            o[2][2] = fmaf(p2, vv.z, o[2][2]); o[2][3] = fmaf(p2, vv.w, o[2][3]);
            o[3][0] = fmaf(p3, vv.x, o[3][0]); o[3][1] = fmaf(p3, vv.y, o[3][1]);
            o[3][2] = fmaf(p3, vv.z, o[3][2]); o[3][3] = fmaf(p3, vv.w, o[3][3]);
        }
        __syncthreads();
    }

    float* Og = g_attn + ((size_t)(b * SEQ + qb * 64)) * D_MODEL + h * HEAD_DIM;
    #pragma unroll
    for (int i = 0; i < 4; i++) {
        int r = tm * 4 + i;
        float inv = 1.0f / row_l[r];
        float4 ov;
        ov.x = o[i][0] * inv; ov.y = o[i][1] * inv;
        ov.z = o[i][2] * inv; ov.w = o[i][3] * inv;
        *(float4*)&Og[(size_t)r * D_MODEL + tn * 4] = ov;
    }
}

// ----------------------------------------------------------------------------
extern "C" void kernel_launch(void* const* d_in, const int* in_sizes, int n_in,
                              void* d_out, int out_size)
{
    const float* x    = (const float*)d_in[0];
    const float* y    = (const float*)d_in[1];
    const float* mask = (const float*)d_in[2];
    const float* Wq   = (const float*)d_in[3];
    const float* bq   = (const float*)d_in[4];
    const float* Wk   = (const float*)d_in[5];
    const float* bk   = (const float*)d_in[6];
    const float* Wv   = (const float*)d_in[7];
    const float* bv   = (const float*)d_in[8];
    const float* Wo   = (const float*)d_in[9];
    const float* bo   = (const float*)d_in[10];
    float* out = (float*)d_out;

    float *gq, *gk, *gv, *ga;
    cudaGetSymbolAddress((void**)&gq, g_q);
    cudaGetSymbolAddress((void**)&gk, g_k);
    cudaGetSymbolAddress((void**)&gv, g_v);
    cudaGetSymbolAddress((void**)&ga, g_attn);

    cudaFuncSetAttribute(flash_attn, cudaFuncAttributeMaxDynamicSharedMemorySize,
                         FA_SMEM_BYTES);

    dim3 ggrid(D_MODEL / BN, M_TOTAL / BM);     // (8, 32)
    gemm_mma<<<ggrid, 256>>>(x, Wq, bq, gq);
    gemm_mma<<<ggrid, 256>>>(y, Wk, bk, gk);
    gemm_mma<<<ggrid, 256>>>(y, Wv, bv, gv);

    dim3 agrid(BATCH * HEADS, SEQ / 64);        // (32, 32)
    flash_attn<<<agrid, 256, FA_SMEM_BYTES>>>(mask);

    gemm_mma<<<ggrid, 256>>>(ga, Wo, bo, out);
}

// round 6
// speedup vs baseline: 2.1092x; 1.5790x over previous
#include <cuda_runtime.h>
#include <cuda_bf16.h>
#include <cstdint>
#include <math.h>

// Problem constants (fixed by the dataset)
#define D_MODEL   1024
#define HEADS     16
#define HEAD_DIM  64
#define BATCH     2
#define SEQ       2048
#define M_TOTAL   (BATCH * SEQ)       // 4096 rows for projection GEMMs

// Scratch: device globals (no allocations allowed)
__device__ float g_q[M_TOTAL * D_MODEL];
__device__ float g_k[M_TOTAL * D_MODEL];
__device__ float g_v[M_TOTAL * D_MODEL];
__device__ float g_attn[M_TOTAL * D_MODEL];

// ============================================================================
// Warp-level MMA helpers (mma.sync + ldmatrix — supported on base sm_103)
// ============================================================================
__device__ __forceinline__ uint32_t smem_u32(const void* p) {
    uint32_t a;
    asm("{ .reg .u64 t; cvta.to.shared.u64 t, %1; cvt.u32.u64 %0, t; }"
        : "=r"(a) : "l"(p));
    return a;
}

__device__ __forceinline__ void ldm_x4(uint32_t* r, uint32_t addr) {
    asm volatile("ldmatrix.sync.aligned.m8n8.x4.shared.b16 {%0,%1,%2,%3}, [%4];"
                 : "=r"(r[0]), "=r"(r[1]), "=r"(r[2]), "=r"(r[3]) : "r"(addr));
}

// D += A(16x16) * B(16x8)  bf16 inputs, fp32 accum
__device__ __forceinline__ void mma16816(float* d, const uint32_t* a, const uint32_t* b) {
    asm volatile(
        "mma.sync.aligned.m16n8k16.row.col.f32.bf16.bf16.f32 "
        "{%0,%1,%2,%3}, {%4,%5,%6,%7}, {%8,%9}, {%0,%1,%2,%3};"
        : "+f"(d[0]), "+f"(d[1]), "+f"(d[2]), "+f"(d[3])
        : "r"(a[0]), "r"(a[1]), "r"(a[2]), "r"(a[3]), "r"(b[0]), "r"(b[1]));
}

// Convert 4 fp32 -> 4 bf16 hi + 4 bf16 lo (residual), store 8B to each tile
__device__ __forceinline__ void cvt_split_store(char* hi_tile, char* lo_tile,
                                                uint32_t off, float4 v) {
    uint32_t h01, h23, l01, l23;
    asm("cvt.rn.bf16x2.f32 %0, %1, %2;" : "=r"(h01) : "f"(v.y), "f"(v.x));
    asm("cvt.rn.bf16x2.f32 %0, %1, %2;" : "=r"(h23) : "f"(v.w), "f"(v.z));
    float r0 = v.x - __uint_as_float(h01 << 16);
    float r1 = v.y - __uint_as_float(h01 & 0xFFFF0000u);
    float r2 = v.z - __uint_as_float(h23 << 16);
    float r3 = v.w - __uint_as_float(h23 & 0xFFFF0000u);
    asm("cvt.rn.bf16x2.f32 %0, %1, %2;" : "=r"(l01) : "f"(r1), "f"(r0));
    asm("cvt.rn.bf16x2.f32 %0, %1, %2;" : "=r"(l23) : "f"(r3), "f"(r2));
    *(uint2*)(hi_tile + off) = make_uint2(h01, h23);
    *(uint2*)(lo_tile + off) = make_uint2(l01, l23);
}

// Split one fp32 into hi/lo bf16, scattered 2-byte stores
__device__ __forceinline__ void split_store1(char* hi, char* lo, uint32_t off, float x) {
    __nv_bfloat16 hb = __float2bfloat16(x);
    float r = x - __bfloat162float(hb);
    __nv_bfloat16 lb = __float2bfloat16(r);
    *(__nv_bfloat16*)(hi + off) = hb;
    *(__nv_bfloat16*)(lo + off) = lb;
}

// Pack two fp32 -> bf16x2 (lo half = first arg) + residual pair
__device__ __forceinline__ void pack_split(float p0, float p1, uint32_t& h, uint32_t& l) {
    asm("cvt.rn.bf16x2.f32 %0, %1, %2;" : "=r"(h) : "f"(p1), "f"(p0));
    float r0 = p0 - __uint_as_float(h << 16);
    float r1 = p1 - __uint_as_float(h & 0xFFFF0000u);
    asm("cvt.rn.bf16x2.f32 %0, %1, %2;" : "=r"(l) : "f"(r1), "f"(r0));
}

// ============================================================================
// GEMM: C[M,N] = A[M,K] @ W[N,K]^T + bias   (M=4096, N=K=1024)  [validated R5]
// ============================================================================
#define BM 128
#define BN 128
#define BK 32
#define KITERS (D_MODEL / BK)       // 32
#define LDT 40                       // tile row stride in halves (80 bytes)
#define TILE_BYTES (128 * LDT * 2)   // 10240

__global__ __launch_bounds__(256) void gemm_mma(
    const float* __restrict__ A,
    const float* __restrict__ W,
    const float* __restrict__ bias,
    float* __restrict__ C)
{
    __shared__ char sm[4 * TILE_BYTES];   // As_hi, As_lo, Bs_hi, Bs_lo
    char* As_hi = sm;
    char* As_lo = sm + TILE_BYTES;
    char* Bs_hi = sm + 2 * TILE_BYTES;
    char* Bs_lo = sm + 3 * TILE_BYTES;

    const int tid    = threadIdx.x;
    const int lane   = tid & 31;
    const int wid    = tid >> 5;
    const int warp_m = wid & 3;
    const int warp_n = wid >> 2;
    const int bm     = blockIdx.y;
    const int bn     = blockIdx.x;

    const float* Ag = A + (size_t)bm * BM * D_MODEL;
    const float* Wg = W + (size_t)bn * BN * D_MODEL;

    uint32_t st_off[4];
    uint32_t gl_off[4];
    #pragma unroll
    for (int i = 0; i < 4; i++) {
        int f = tid + i * 256;
        int r = f >> 3, c4 = (f & 7) * 4;
        st_off[i] = (uint32_t)(r * (LDT * 2) + c4 * 2);
        gl_off[i] = (uint32_t)(r * D_MODEL + c4);
    }

    const uint32_t a_base = smem_u32(As_hi);
    const uint32_t a_off =
        (uint32_t)((warp_m * 32 + (lane & 7) + ((lane >> 3) & 1) * 8) * (LDT * 2)
                   + (lane >> 4) * 16);
    const uint32_t b_off =
        (uint32_t)((warp_n * 64 + (lane & 7)) * (LDT * 2) + (lane >> 3) * 16);

    float acc[2][8][4];
    #pragma unroll
    for (int mt = 0; mt < 2; mt++)
        #pragma unroll
        for (int nt = 0; nt < 8; nt++)
            #pragma unroll
            for (int j = 0; j < 4; j++) acc[mt][nt][j] = 0.0f;

    float4 pa[4], pb[4];
    #pragma unroll
    for (int i = 0; i < 4; i++) {
        pa[i] = *(const float4*)(Ag + gl_off[i]);
        pb[i] = *(const float4*)(Wg + gl_off[i]);
    }

    for (int it = 0; it < KITERS; it++) {
        #pragma unroll
        for (int i = 0; i < 4; i++) {
            cvt_split_store(As_hi, As_lo, st_off[i], pa[i]);
            cvt_split_store(Bs_hi, Bs_lo, st_off[i], pb[i]);
        }
        __syncthreads();

        if (it + 1 < KITERS) {
            const uint32_t g = (uint32_t)((it + 1) * BK);
            #pragma unroll
            for (int i = 0; i < 4; i++) {
                pa[i] = *(const float4*)(Ag + gl_off[i] + g);
                pb[i] = *(const float4*)(Wg + gl_off[i] + g);
            }
        }

        uint32_t ah[2][2][4], al[2][2][4];
        #pragma unroll
        for (int ks = 0; ks < 2; ks++)
            #pragma unroll
            for (int mt = 0; mt < 2; mt++) {
                uint32_t off = a_off + (uint32_t)(mt * 16 * (LDT * 2) + ks * 32);
                ldm_x4(ah[ks][mt], a_base + off);
                ldm_x4(al[ks][mt], a_base + TILE_BYTES + off);
            }

        #pragma unroll
        for (int nt = 0; nt < 8; nt++) {
            uint32_t off = b_off + (uint32_t)(nt * 8 * (LDT * 2));
            uint32_t bh[4], bl[4];
            ldm_x4(bh, a_base + 2 * TILE_BYTES + off);
            ldm_x4(bl, a_base + 3 * TILE_BYTES + off);
            #pragma unroll
            for (int ks = 0; ks < 2; ks++)
                #pragma unroll
                for (int mt = 0; mt < 2; mt++) {
                    mma16816(acc[mt][nt], ah[ks][mt], bh + ks * 2);
                    mma16816(acc[mt][nt], ah[ks][mt], bl + ks * 2);
                    mma16816(acc[mt][nt], al[ks][mt], bh + ks * 2);
                }
        }
        __syncthreads();
    }

    const int lrow = lane >> 2;
    const int lcol = (lane & 3) * 2;
    #pragma unroll
    for (int mt = 0; mt < 2; mt++) {
        const int r0 = bm * BM + warp_m * 32 + mt * 16 + lrow;
        #pragma unroll
        for (int nt = 0; nt < 8; nt++) {
            const int cg = bn * BN + warp_n * 64 + nt * 8 + lcol;
            const float b0 = bias[cg], b1 = bias[cg + 1];
            float2 v0 = make_float2(acc[mt][nt][0] + b0, acc[mt][nt][1] + b1);
            float2 v1 = make_float2(acc[mt][nt][2] + b0, acc[mt][nt][3] + b1);
            *(float2*)(C + (size_t)r0 * D_MODEL + cg)       = v0;
            *(float2*)(C + (size_t)(r0 + 8) * D_MODEL + cg) = v1;
        }
    }
}

// ============================================================================
// Flash attention on tensor cores (mma.sync, bf16 hi/lo 3-pass).
// Block: 128 q-rows x one (b,h). 8 warps, warp owns 16 rows.
// KV tiles of 64. Grid: (B*H, SEQ/128).
// ============================================================================
#define A_LDB   144                  // smem row stride bytes (72 halves)
#define OFF_QH  0
#define OFF_QL  18432
#define OFF_KH  36864
#define OFF_KL  46080
#define OFF_VH  55296
#define OFF_VL  64512
#define ATT_SMEM 73728

__global__ __launch_bounds__(256) void flash_attn_mma(const float* __restrict__ mask)
{
    extern __shared__ char sm[];
    const uint32_t smb = smem_u32(sm);
    const int tid  = threadIdx.x;
    const int lane = tid & 31;
    const int wid  = tid >> 5;
    const int bh   = blockIdx.x;
    const int b    = bh >> 4;            // / HEADS
    const int h    = bh & 15;
    const int q0   = blockIdx.y * 128;

    const float* Qg = g_q + ((size_t)(b * SEQ + q0)) * D_MODEL + h * HEAD_DIM;
    const float* Kg = g_k + ((size_t)b * SEQ) * D_MODEL + h * HEAD_DIM;
    const float* Vg = g_v + ((size_t)b * SEQ) * D_MODEL + h * HEAD_DIM;
    const float* Mg = mask + ((size_t)b * SEQ + q0) * SEQ;

    // Stage Q (hi/lo split), 128 rows x 64 cols
    #pragma unroll
    for (int i = 0; i < 8; i++) {
        int f = tid + i * 256;
        int r = f >> 4, c4 = (f & 15) * 4;
        float4 v = *(const float4*)(Qg + (size_t)r * D_MODEL + c4);
        cvt_split_store(sm + OFF_QH, sm + OFF_QL, (uint32_t)(r * A_LDB + c4 * 2), v);
    }
    __syncthreads();

    // Hoist Q fragments to registers (whole KV loop)
    const int qr = wid * 16;
    uint32_t ah[4][4], al[4][4];
    {
        uint32_t base = smb + (uint32_t)((qr + (lane & 15)) * A_LDB + (lane >> 4) * 16);
        #pragma unroll
        for (int ks = 0; ks < 4; ks++) {
            ldm_x4(ah[ks], base + OFF_QH + ks * 32);
            ldm_x4(al[ks], base + OFF_QL + ks * 32);
        }
    }

    const int lrow = lane >> 2;
    const int lcol = (lane & 3) * 2;
    const uint32_t frag_base = smb + (uint32_t)((lane & 7) * A_LDB + (lane >> 3) * 16);

    float o[8][4];
    #pragma unroll
    for (int dt = 0; dt < 8; dt++)
        #pragma unroll
        for (int j = 0; j < 4; j++) o[dt][j] = 0.0f;
    float m0 = -1e30f, m8 = -1e30f, l0 = 0.0f, l8 = 0.0f;

    for (int kb = 0; kb < SEQ / 64; kb++) {
        __syncthreads();
        // Stage K tile (hi/lo), rows j, cols d
        #pragma unroll
        for (int i = 0; i < 4; i++) {
            int f = tid + i * 256;
            int r = f >> 4, c4 = (f & 15) * 4;
            float4 v = *(const float4*)(Kg + (size_t)(kb * 64 + r) * D_MODEL + c4);
            cvt_split_store(sm + OFF_KH, sm + OFF_KL, (uint32_t)(r * A_LDB + c4 * 2), v);
        }
        // Stage V transposed: Vt[d][j]
        #pragma unroll
        for (int i = 0; i < 4; i++) {
            int f = tid + i * 256;
            int j = f >> 4, d4 = (f & 15) * 4;
            float4 v = *(const float4*)(Vg + (size_t)(kb * 64 + j) * D_MODEL + d4);
            split_store1(sm + OFF_VH, sm + OFF_VL, (uint32_t)((d4 + 0) * A_LDB + j * 2), v.x);
            split_store1(sm + OFF_VH, sm + OFF_VL, (uint32_t)((d4 + 1) * A_LDB + j * 2), v.y);
            split_store1(sm + OFF_VH, sm + OFF_VL, (uint32_t)((d4 + 2) * A_LDB + j * 2), v.z);
            split_store1(sm + OFF_VH, sm + OFF_VL, (uint32_t)((d4 + 3) * A_LDB + j * 2), v.w);
        }
        __syncthreads();

        // S = Q K^T (3-pass hi/lo), warp tile 16x64
        float s[8][4];
        #pragma unroll
        for (int nt = 0; nt < 8; nt++)
            #pragma unroll
            for (int j = 0; j < 4; j++) s[nt][j] = 0.0f;

        #pragma unroll
        for (int nt = 0; nt < 8; nt++) {
            uint32_t ka = frag_base + (uint32_t)(nt * 8 * A_LDB);
            uint32_t kh[8], kl[8];
            ldm_x4(kh,     ka + OFF_KH);
            ldm_x4(kh + 4, ka + OFF_KH + 64);
            ldm_x4(kl,     ka + OFF_KL);
            ldm_x4(kl + 4, ka + OFF_KL + 64);
            #pragma unroll
            for (int ks = 0; ks < 4; ks++) {
                mma16816(s[nt], ah[ks], kh + ks * 2);
                mma16816(s[nt], ah[ks], kl + ks * 2);
                mma16816(s[nt], al[ks], kh + ks * 2);
            }
        }

        // Scale + mask + row max
        const float* mrow = Mg + (size_t)kb * 64;
        float tmax0 = -1e30f, tmax8 = -1e30f;
        #pragma unroll
        for (int nt = 0; nt < 8; nt++) {
            int c = nt * 8 + lcol;
            float2 mk0 = *(const float2*)(mrow + (size_t)(qr + lrow) * SEQ + c);
            float2 mk8 = *(const float2*)(mrow + (size_t)(qr + lrow + 8) * SEQ + c);
            s[nt][0] = fmaf(s[nt][0], 0.125f, (mk0.x - 1.0f) * 1e9f);
            s[nt][1] = fmaf(s[nt][1], 0.125f, (mk0.y - 1.0f) * 1e9f);
            s[nt][2] = fmaf(s[nt][2], 0.125f, (mk8.x - 1.0f) * 1e9f);
            s[nt][3] = fmaf(s[nt][3], 0.125f, (mk8.y - 1.0f) * 1e9f);
            tmax0 = fmaxf(tmax0, fmaxf(s[nt][0], s[nt][1]));
            tmax8 = fmaxf(tmax8, fmaxf(s[nt][2], s[nt][3]));
        }
        tmax0 = fmaxf(tmax0, __shfl_xor_sync(0xffffffffu, tmax0, 1));
        tmax0 = fmaxf(tmax0, __shfl_xor_sync(0xffffffffu, tmax0, 2));
        tmax8 = fmaxf(tmax8, __shfl_xor_sync(0xffffffffu, tmax8, 1));
        tmax8 = fmaxf(tmax8, __shfl_xor_sync(0xffffffffu, tmax8, 2));

        float mn0 = fmaxf(m0, tmax0), mn8 = fmaxf(m8, tmax8);
        float al0 = __expf(m0 - mn0), al8 = __expf(m8 - mn8);
        m0 = mn0; m8 = mn8;

        // exp, sums, and P fragments (hi/lo) in registers
        float sum0 = 0.0f, sum8 = 0.0f;
        uint32_t pah[4][4], pal[4][4];
        #pragma unroll
        for (int nt = 0; nt < 8; nt++) {
            float p0 = __expf(s[nt][0] - mn0);
            float p1 = __expf(s[nt][1] - mn0);
            float p2 = __expf(s[nt][2] - mn8);
            float p3 = __expf(s[nt][3] - mn8);
            sum0 += p0 + p1;
            sum8 += p2 + p3;
            int ks = nt >> 1, slot = (nt & 1) * 2;
            pack_split(p0, p1, pah[ks][slot],     pal[ks][slot]);
            pack_split(p2, p3, pah[ks][slot + 1], pal[ks][slot + 1]);
        }
        sum0 += __shfl_xor_sync(0xffffffffu, sum0, 1);
        sum0 += __shfl_xor_sync(0xffffffffu, sum0, 2);
        sum8 += __shfl_xor_sync(0xffffffffu, sum8, 1);
        sum8 += __shfl_xor_sync(0xffffffffu, sum8, 2);
        l0 = l0 * al0 + sum0;
        l8 = l8 * al8 + sum8;

        // Rescale O, then O += P @ V (3-pass hi/lo)
        #pragma unroll
        for (int dt = 0; dt < 8; dt++) {
            o[dt][0] *= al0; o[dt][1] *= al0;
            o[dt][2] *= al8; o[dt][3] *= al8;
        }
        #pragma unroll
        for (int dt = 0; dt < 8; dt++) {
            uint32_t va = frag_base + (uint32_t)(dt * 8 * A_LDB);
            uint32_t vh[8], vl[8];
            ldm_x4(vh,     va + OFF_VH);
            ldm_x4(vh + 4, va + OFF_VH + 64);
            ldm_x4(vl,     va + OFF_VL);
            ldm_x4(vl + 4, va + OFF_VL + 64);
            #pragma unroll
            for (int ks = 0; ks < 4; ks++) {
                mma16816(o[dt], pah[ks], vh + ks * 2);
                mma16816(o[dt], pah[ks], vl + ks * 2);
                mma16816(o[dt], pal[ks], vh + ks * 2);
            }
        }
    }

    // Normalize and store
    const float inv0 = 1.0f / l0;
    const float inv8 = 1.0f / l8;
    float* Og = g_attn + ((size_t)(b * SEQ + q0 + qr)) * D_MODEL + h * HEAD_DIM;
    #pragma unroll
    for (int dt = 0; dt < 8; dt++) {
        int c = dt * 8 + lcol;
        float2 v0 = make_float2(o[dt][0] * inv0, o[dt][1] * inv0);
        float2 v1 = make_float2(o[dt][2] * inv8, o[dt][3] * inv8);
        *(float2*)(Og + (size_t)lrow * D_MODEL + c)       = v0;
        *(float2*)(Og + (size_t)(lrow + 8) * D_MODEL + c) = v1;
    }
}

// ----------------------------------------------------------------------------
extern "C" void kernel_launch(void* const* d_in, const int* in_sizes, int n_in,
                              void* d_out, int out_size)
{
    const float* x    = (const float*)d_in[0];
    const float* y    = (const float*)d_in[1];
    const float* mask = (const float*)d_in[2];
    const float* Wq   = (const float*)d_in[3];
    const float* bq   = (const float*)d_in[4];
    const float* Wk   = (const float*)d_in[5];
    const float* bk   = (const float*)d_in[6];
    const float* Wv   = (const float*)d_in[7];
    const float* bv   = (const float*)d_in[8];
    const float* Wo   = (const float*)d_in[9];
    const float* bo   = (const float*)d_in[10];
    float* out = (float*)d_out;

    float *gq, *gk, *gv, *ga;
    cudaGetSymbolAddress((void**)&gq, g_q);
    cudaGetSymbolAddress((void**)&gk, g_k);
    cudaGetSymbolAddress((void**)&gv, g_v);
    cudaGetSymbolAddress((void**)&ga, g_attn);

    cudaFuncSetAttribute(flash_attn_mma,
                         cudaFuncAttributeMaxDynamicSharedMemorySize, ATT_SMEM);

    dim3 ggrid(D_MODEL / BN, M_TOTAL / BM);     // (8, 32)
    gemm_mma<<<ggrid, 256>>>(x, Wq, bq, gq);
    gemm_mma<<<ggrid, 256>>>(y, Wk, bk, gk);
    gemm_mma<<<ggrid, 256>>>(y, Wv, bv, gv);

    dim3 agrid(BATCH * HEADS, SEQ / 128);       // (32, 16)
    flash_attn_mma<<<agrid, 256, ATT_SMEM>>>(mask);

    gemm_mma<<<ggrid, 256>>>(ga, Wo, bo, out);
}

// round 10
// speedup vs baseline: 2.1913x; 1.0389x over previous
#include <cuda_runtime.h>
#include <cuda_bf16.h>
#include <cstdint>
#include <math.h>

// Problem constants (fixed by the dataset)
#define D_MODEL   1024
#define HEADS     16
#define HEAD_DIM  64
#define BATCH     2
#define SEQ       2048
#define M_TOTAL   (BATCH * SEQ)       // 4096 rows for projection GEMMs

// Scratch: device globals (no allocations allowed)
__device__ __nv_bfloat16 g_qh[M_TOTAL * D_MODEL];
__device__ __nv_bfloat16 g_ql[M_TOTAL * D_MODEL];
__device__ __nv_bfloat16 g_kh[M_TOTAL * D_MODEL];
__device__ __nv_bfloat16 g_kl[M_TOTAL * D_MODEL];
__device__ __nv_bfloat16 g_vh[M_TOTAL * D_MODEL];
__device__ __nv_bfloat16 g_vl[M_TOTAL * D_MODEL];
__device__ float         g_attn[M_TOTAL * D_MODEL];

// ============================================================================
// Warp-level MMA helpers (mma.sync + ldmatrix + cp.async — base sm_103)
// ============================================================================
__device__ __forceinline__ uint32_t smem_u32(const void* p) {
    uint32_t a;
    asm("{ .reg .u64 t; cvta.to.shared.u64 t, %1; cvt.u32.u64 %0, t; }"
        : "=r"(a) : "l"(p));
    return a;
}

__device__ __forceinline__ void ldm_x4(uint32_t* r, uint32_t addr) {
    asm volatile("ldmatrix.sync.aligned.m8n8.x4.shared.b16 {%0,%1,%2,%3}, [%4];"
                 : "=r"(r[0]), "=r"(r[1]), "=r"(r[2]), "=r"(r[3]) : "r"(addr));
}

__device__ __forceinline__ void ldm_x4_trans(uint32_t* r, uint32_t addr) {
    asm volatile("ldmatrix.sync.aligned.m8n8.x4.trans.shared.b16 {%0,%1,%2,%3}, [%4];"
                 : "=r"(r[0]), "=r"(r[1]), "=r"(r[2]), "=r"(r[3]) : "r"(addr));
}

// D += A(16x16) * B(16x8)  bf16 inputs, fp32 accum
__device__ __forceinline__ void mma16816(float* d, const uint32_t* a, const uint32_t* b) {
    asm volatile(
        "mma.sync.aligned.m16n8k16.row.col.f32.bf16.bf16.f32 "
        "{%0,%1,%2,%3}, {%4,%5,%6,%7}, {%8,%9}, {%0,%1,%2,%3};"
        : "+f"(d[0]), "+f"(d[1]), "+f"(d[2]), "+f"(d[3])
        : "r"(a[0]), "r"(a[1]), "r"(a[2]), "r"(a[3]), "r"(b[0]), "r"(b[1]));
}

__device__ __forceinline__ void cpa16(uint32_t dst, const void* src) {
    asm volatile("cp.async.ca.shared.global [%0], [%1], 16;"
                 :: "r"(dst), "l"(src) : "memory");
}
#define CP_COMMIT() asm volatile("cp.async.commit_group;" ::: "memory")
#define CP_WAIT0()  asm volatile("cp.async.wait_group 0;" ::: "memory")

// Convert 4 fp32 -> 4 bf16 hi + 4 bf16 lo (residual), store 8B to each tile
__device__ __forceinline__ void cvt_split_store(char* hi_tile, char* lo_tile,
                                                uint32_t off, float4 v) {
    uint32_t h01, h23, l01, l23;
    asm("cvt.rn.bf16x2.f32 %0, %1, %2;" : "=r"(h01) : "f"(v.y), "f"(v.x));
    asm("cvt.rn.bf16x2.f32 %0, %1, %2;" : "=r"(h23) : "f"(v.w), "f"(v.z));
    float r0 = v.x - __uint_as_float(h01 << 16);
    float r1 = v.y - __uint_as_float(h01 & 0xFFFF0000u);
    float r2 = v.z - __uint_as_float(h23 << 16);
    float r3 = v.w - __uint_as_float(h23 & 0xFFFF0000u);
    asm("cvt.rn.bf16x2.f32 %0, %1, %2;" : "=r"(l01) : "f"(r1), "f"(r0));
    asm("cvt.rn.bf16x2.f32 %0, %1, %2;" : "=r"(l23) : "f"(r3), "f"(r2));
    *(uint2*)(hi_tile + off) = make_uint2(h01, h23);
    *(uint2*)(lo_tile + off) = make_uint2(l01, l23);
}

// Pack two fp32 -> bf16x2 (lo half = first arg) + residual pair
__device__ __forceinline__ void pack_split(float p0, float p1, uint32_t& h, uint32_t& l) {
    asm("cvt.rn.bf16x2.f32 %0, %1, %2;" : "=r"(h) : "f"(p1), "f"(p0));
    float r0 = p0 - __uint_as_float(h << 16);
    float r1 = p1 - __uint_as_float(h & 0xFFFF0000u);
    asm("cvt.rn.bf16x2.f32 %0, %1, %2;" : "=r"(l) : "f"(r1), "f"(r0));
}

// ============================================================================
// GEMM: C[M,N] = A[M,K] @ W[N,K]^T + bias   (M=4096, N=K=1024)  [validated R5]
// SPLIT=true: write hi/lo bf16 arrays. SPLIT=false: write fp32 C.
// ============================================================================
#define BM 128
#define BN 128
#define BK 32
#define KITERS (D_MODEL / BK)       // 32
#define LDT 40                       // tile row stride in halves (80 bytes)
#define TILE_BYTES (128 * LDT * 2)   // 10240

template<bool SPLIT>
__global__ __launch_bounds__(256) void gemm_mma(
    const float* __restrict__ A,
    const float* __restrict__ W,
    const float* __restrict__ bias,
    float* __restrict__ C,
    __nv_bfloat16* __restrict__ Chi,
    __nv_bfloat16* __restrict__ Clo)
{
    __shared__ char sm[4 * TILE_BYTES];   // As_hi, As_lo, Bs_hi, Bs_lo
    char* As_hi = sm;
    char* As_lo = sm + TILE_BYTES;
    char* Bs_hi = sm + 2 * TILE_BYTES;
    char* Bs_lo = sm + 3 * TILE_BYTES;

    const int tid    = threadIdx.x;
    const int lane   = tid & 31;
    const int wid    = tid >> 5;
    const int warp_m = wid & 3;
    const int warp_n = wid >> 2;
    const int bm     = blockIdx.y;
    const int bn     = blockIdx.x;

    const float* Ag = A + (size_t)bm * BM * D_MODEL;
    const float* Wg = W + (size_t)bn * BN * D_MODEL;

    uint32_t st_off[4];
    uint32_t gl_off[4];
    #pragma unroll
    for (int i = 0; i < 4; i++) {
        int f = tid + i * 256;
        int r = f >> 3, c4 = (f & 7) * 4;
        st_off[i] = (uint32_t)(r * (LDT * 2) + c4 * 2);
        gl_off[i] = (uint32_t)(r * D_MODEL + c4);
    }

    const uint32_t a_base = smem_u32(As_hi);
    const uint32_t a_off =
        (uint32_t)((warp_m * 32 + (lane & 7) + ((lane >> 3) & 1) * 8) * (LDT * 2)
                   + (lane >> 4) * 16);
    const uint32_t b_off =
        (uint32_t)((warp_n * 64 + (lane & 7)) * (LDT * 2) + (lane >> 3) * 16);

    float acc[2][8][4];
    #pragma unroll
    for (int mt = 0; mt < 2; mt++)
        #pragma unroll
        for (int nt = 0; nt < 8; nt++)
            #pragma unroll
            for (int j = 0; j < 4; j++) acc[mt][nt][j] = 0.0f;

    float4 pa[4], pb[4];
    #pragma unroll
    for (int i = 0; i < 4; i++) {
        pa[i] = *(const float4*)(Ag + gl_off[i]);
        pb[i] = *(const float4*)(Wg + gl_off[i]);
    }

    for (int it = 0; it < KITERS; it++) {
        #pragma unroll
        for (int i = 0; i < 4; i++) {
            cvt_split_store(As_hi, As_lo, st_off[i], pa[i]);
            cvt_split_store(Bs_hi, Bs_lo, st_off[i], pb[i]);
        }
        __syncthreads();

        if (it + 1 < KITERS) {
            const uint32_t g = (uint32_t)((it + 1) * BK);
            #pragma unroll
            for (int i = 0; i < 4; i++) {
                pa[i] = *(const float4*)(Ag + gl_off[i] + g);
                pb[i] = *(const float4*)(Wg + gl_off[i] + g);
            }
        }

        uint32_t ah[2][2][4], al[2][2][4];
        #pragma unroll
        for (int ks = 0; ks < 2; ks++)
            #pragma unroll
            for (int mt = 0; mt < 2; mt++) {
                uint32_t off = a_off + (uint32_t)(mt * 16 * (LDT * 2) + ks * 32);
                ldm_x4(ah[ks][mt], a_base + off);
                ldm_x4(al[ks][mt], a_base + TILE_BYTES + off);
            }

        #pragma unroll
        for (int nt = 0; nt < 8; nt++) {
            uint32_t off = b_off + (uint32_t)(nt * 8 * (LDT * 2));
            uint32_t bh[4], bl[4];
            ldm_x4(bh, a_base + 2 * TILE_BYTES + off);
            ldm_x4(bl, a_base + 3 * TILE_BYTES + off);
            #pragma unroll
            for (int ks = 0; ks < 2; ks++)
                #pragma unroll
                for (int mt = 0; mt < 2; mt++) {
                    mma16816(acc[mt][nt], ah[ks][mt], bh + ks * 2);
                    mma16816(acc[mt][nt], ah[ks][mt], bl + ks * 2);
                    mma16816(acc[mt][nt], al[ks][mt], bh + ks * 2);
                }
        }
        __syncthreads();
    }

    const int lrow = lane >> 2;
    const int lcol = (lane & 3) * 2;
    #pragma unroll
    for (int mt = 0; mt < 2; mt++) {
        const int r0 = bm * BM + warp_m * 32 + mt * 16 + lrow;
        #pragma unroll
        for (int nt = 0; nt < 8; nt++) {
            const int cg = bn * BN + warp_n * 64 + nt * 8 + lcol;
            const float b0 = bias[cg], b1 = bias[cg + 1];
            float c00 = acc[mt][nt][0] + b0, c01 = acc[mt][nt][1] + b1;
            float c10 = acc[mt][nt][2] + b0, c11 = acc[mt][nt][3] + b1;
            if (SPLIT) {
                uint32_t h0, l0, h1, l1;
                pack_split(c00, c01, h0, l0);
                pack_split(c10, c11, h1, l1);
                *(uint32_t*)(Chi + (size_t)r0 * D_MODEL + cg)       = h0;
                *(uint32_t*)(Clo + (size_t)r0 * D_MODEL + cg)       = l0;
                *(uint32_t*)(Chi + (size_t)(r0 + 8) * D_MODEL + cg) = h1;
                *(uint32_t*)(Clo + (size_t)(r0 + 8) * D_MODEL + cg) = l1;
            } else {
                *(float2*)(C + (size_t)r0 * D_MODEL + cg)       = make_float2(c00, c01);
                *(float2*)(C + (size_t)(r0 + 8) * D_MODEL + cg) = make_float2(c10, c11);
            }
        }
    }
}

// ============================================================================
// Flash attention on tensor cores. Inputs pre-split bf16 hi/lo.
// Block: 128 q-rows x one (b,h). 8 warps, warp owns 16 rows.
// KV tiles of 64, cp.async double-buffered. Grid: (B*H, SEQ/128).
// ============================================================================
#define LDB     144                  // smem row stride bytes (72 halves)
#define OFF_QH  0
#define OFF_QL  18432
#define OFF_KV  36864                // KV buffers start
#define KV_KH   0
#define KV_KL   9216
#define KV_VH   18432
#define KV_VL   27648
#define KVBUF   36864                // per-buffer size
#define ATT_SMEM (OFF_KV + 2 * KVBUF)   // 110592

__device__ __forceinline__ void stage_kv_tile(
    uint32_t bufb,
    const __nv_bfloat16* kh, const __nv_bfloat16* kl,
    const __nv_bfloat16* vh, const __nv_bfloat16* vl,
    int tid)
{
    #pragma unroll
    for (int i = 0; i < 2; i++) {
        int f = tid + i * 256;
        int r = f >> 3, c = f & 7;
        uint32_t so = (uint32_t)(r * LDB + c * 16);
        size_t go = (size_t)r * D_MODEL + c * 8;
        cpa16(bufb + KV_KH + so, kh + go);
        cpa16(bufb + KV_KL + so, kl + go);
        cpa16(bufb + KV_VH + so, vh + go);
        cpa16(bufb + KV_VL + so, vl + go);
    }
}

__global__ __launch_bounds__(256) void flash_attn_mma(const float* __restrict__ mask)
{
    extern __shared__ char sm[];
    const uint32_t smb = smem_u32(sm);
    const int tid  = threadIdx.x;
    const int lane = tid & 31;
    const int wid  = tid >> 5;
    const int bh   = blockIdx.x;
    const int b    = bh >> 4;            // / HEADS
    const int h    = bh & 15;
    const int q0   = blockIdx.y * 128;

    const size_t qrow0 = (size_t)(b * SEQ + q0);
    const size_t krow0 = (size_t)b * SEQ;
    const __nv_bfloat16* Qh = g_qh + qrow0 * D_MODEL + h * HEAD_DIM;
    const __nv_bfloat16* Ql = g_ql + qrow0 * D_MODEL + h * HEAD_DIM;
    const __nv_bfloat16* Kh = g_kh + krow0 * D_MODEL + h * HEAD_DIM;
    const __nv_bfloat16* Kl = g_kl + krow0 * D_MODEL + h * HEAD_DIM;
    const __nv_bfloat16* Vh = g_vh + krow0 * D_MODEL + h * HEAD_DIM;
    const __nv_bfloat16* Vl = g_vl + krow0 * D_MODEL + h * HEAD_DIM;
    const float* Mg = mask + (qrow0) * SEQ;

    // Stage Q (16B copies) + KV tile 0
    #pragma unroll
    for (int i = 0; i < 4; i++) {
        int f = tid + i * 256;
        int r = f >> 3, c = f & 7;
        uint32_t so = (uint32_t)(r * LDB + c * 16);
        size_t go = (size_t)r * D_MODEL + c * 8;
        cpa16(smb + OFF_QH + so, Qh + go);
        cpa16(smb + OFF_QL + so, Ql + go);
    }
    stage_kv_tile(smb + OFF_KV, Kh, Kl, Vh, Vl, tid);
    CP_COMMIT();
    CP_WAIT0();
    __syncthreads();

    // Hoist Q fragments to registers (whole KV loop)
    const int qr = wid * 16;
    uint32_t ah[4][4], al[4][4];
    {
        uint32_t base = smb + (uint32_t)((qr + (lane & 15)) * LDB + (lane >> 4) * 16);
        #pragma unroll
        for (int ks = 0; ks < 4; ks++) {
            ldm_x4(ah[ks], base + OFF_QH + ks * 32);
            ldm_x4(al[ks], base + OFF_QL + ks * 32);
        }
    }

    // Prefetch KV tile 1 into buffer 1
    stage_kv_tile(smb + OFF_KV + KVBUF, Kh + 64 * D_MODEL, Kl + 64 * D_MODEL,
                  Vh + 64 * D_MODEL, Vl + 64 * D_MODEL, tid);
    CP_COMMIT();

    const int lrow = lane >> 2;
    const int lcol = (lane & 3) * 2;
    const uint32_t kfrag = (uint32_t)((lane & 7) * LDB + (lane >> 3) * 16);

    float o[8][4];
    #pragma unroll
    for (int dt = 0; dt < 8; dt++)
        #pragma unroll
        for (int j = 0; j < 4; j++) o[dt][j] = 0.0f;
    float m0 = -1e30f, m8 = -1e30f, l0 = 0.0f, l8 = 0.0f;

    for (int kb = 0; kb < SEQ / 64; kb++) {
        if (kb > 0) {
            CP_WAIT0();
            __syncthreads();
        }
        if (kb >= 1 && kb + 1 < SEQ / 64) {
            size_t off = (size_t)(kb + 1) * 64 * D_MODEL;
            stage_kv_tile(smb + OFF_KV + ((kb + 1) & 1) * KVBUF,
                          Kh + off, Kl + off, Vh + off, Vl + off, tid);
            CP_COMMIT();
        }
        const uint32_t bufb = smb + OFF_KV + (kb & 1) * KVBUF;

        // S = Q K^T (3-pass hi/lo), warp tile 16x64
        float s[8][4];
        #pragma unroll
        for (int nt = 0; nt < 8; nt++)
            #pragma unroll
            for (int j = 0; j < 4; j++) s[nt][j] = 0.0f;

        #pragma unroll
        for (int nt = 0; nt < 8; nt++) {
            uint32_t ka = bufb + kfrag + (uint32_t)(nt * 8 * LDB);
            uint32_t kh[8], kl[8];
            ldm_x4(kh,     ka + KV_KH);
            ldm_x4(kh + 4, ka + KV_KH + 64);
            ldm_x4(kl,     ka + KV_KL);
            ldm_x4(kl + 4, ka + KV_KL + 64);
            #pragma unroll
            for (int ks = 0; ks < 4; ks++) {
                mma16816(s[nt], ah[ks], kh + ks * 2);
                mma16816(s[nt], ah[ks], kl + ks * 2);
                mma16816(s[nt], al[ks], kh + ks * 2);
            }
        }

        // Scale + mask + row max
        const float* mrow = Mg + (size_t)kb * 64;
        float tmax0 = -1e30f, tmax8 = -1e30f;
        #pragma unroll
        for (int nt = 0; nt < 8; nt++) {
            int c = nt * 8 + lcol;
            float2 mk0 = *(const float2*)(mrow + (size_t)(qr + lrow) * SEQ + c);
            float2 mk8 = *(const float2*)(mrow + (size_t)(qr + lrow + 8) * SEQ + c);
            s[nt][0] = fmaf(s[nt][0], 0.125f, (mk0.x - 1.0f) * 1e9f);
            s[nt][1] = fmaf(s[nt][1], 0.125f, (mk0.y - 1.0f) * 1e9f);
            s[nt][2] = fmaf(s[nt][2], 0.125f, (mk8.x - 1.0f) * 1e9f);
            s[nt][3] = fmaf(s[nt][3], 0.125f, (mk8.y - 1.0f) * 1e9f);
            tmax0 = fmaxf(tmax0, fmaxf(s[nt][0], s[nt][1]));
            tmax8 = fmaxf(tmax8, fmaxf(s[nt][2], s[nt][3]));
        }
        tmax0 = fmaxf(tmax0, __shfl_xor_sync(0xffffffffu, tmax0, 1));
        tmax0 = fmaxf(tmax0, __shfl_xor_sync(0xffffffffu, tmax0, 2));
        tmax8 = fmaxf(tmax8, __shfl_xor_sync(0xffffffffu, tmax8, 1));
        tmax8 = fmaxf(tmax8, __shfl_xor_sync(0xffffffffu, tmax8, 2));

        float mn0 = fmaxf(m0, tmax0), mn8 = fmaxf(m8, tmax8);
        float al0 = __expf(m0 - mn0), al8 = __expf(m8 - mn8);
        m0 = mn0; m8 = mn8;

        // exp, sums, and P fragments (hi/lo) in registers
        float sum0 = 0.0f, sum8 = 0.0f;
        uint32_t pah[4][4], pal[4][4];
        #pragma unroll
        for (int nt = 0; nt < 8; nt++) {
            float p0 = __expf(s[nt][0] - mn0);
            float p1 = __expf(s[nt][1] - mn0);
            float p2 = __expf(s[nt][2] - mn8);
            float p3 = __expf(s[nt][3] - mn8);
            sum0 += p0 + p1;
            sum8 += p2 + p3;
            int ks = nt >> 1, slot = (nt & 1) * 2;
            pack_split(p0, p1, pah[ks][slot],     pal[ks][slot]);
            pack_split(p2, p3, pah[ks][slot + 1], pal[ks][slot + 1]);
        }
        sum0 += __shfl_xor_sync(0xffffffffu, sum0, 1);
        sum0 += __shfl_xor_sync(0xffffffffu, sum0, 2);
        sum8 += __shfl_xor_sync(0xffffffffu, sum8, 1);
        sum8 += __shfl_xor_sync(0xffffffffu, sum8, 2);
        l0 = l0 * al0 + sum0;
        l8 = l8 * al8 + sum8;

        // Rescale O, then O += P @ V (3-pass hi/lo, V via ldmatrix.trans)
        #pragma unroll
        for (int dt = 0; dt < 8; dt++) {
            o[dt][0] *= al0; o[dt][1] *= al0;
            o[dt][2] *= al8; o[dt][3] *= al8;
        }
        #pragma unroll
        for (int dt = 0; dt < 8; dt++) {
            uint32_t va = bufb + (uint32_t)(lane * LDB + dt * 16);
            uint32_t vh[8], vl[8];
            ldm_x4_trans(vh,     va + KV_VH);
            ldm_x4_trans(vh + 4, va + KV_VH + 32 * LDB);
            ldm_x4_trans(vl,     va + KV_VL);
            ldm_x4_trans(vl + 4, va + KV_VL + 32 * LDB);
            #pragma unroll
            for (int ks = 0; ks < 4; ks++) {
                mma16816(o[dt], pah[ks], vh + ks * 2);
                mma16816(o[dt], pah[ks], vl + ks * 2);
                mma16816(o[dt], pal[ks], vh + ks * 2);
            }
        }
    }

    // Normalize and store
    const float inv0 = 1.0f / l0;
    const float inv8 = 1.0f / l8;
    float* Og = g_attn + (qrow0 + qr) * D_MODEL + h * HEAD_DIM;
    #pragma unroll
    for (int dt = 0; dt < 8; dt++) {
        int c = dt * 8 + lcol;
        float2 v0 = make_float2(o[dt][0] * inv0, o[dt][1] * inv0);
        float2 v1 = make_float2(o[dt][2] * inv8, o[dt][3] * inv8);
        *(float2*)(Og + (size_t)lrow * D_MODEL + c)       = v0;
        *(float2*)(Og + (size_t)(lrow + 8) * D_MODEL + c) = v1;
    }
}

// ----------------------------------------------------------------------------
extern "C" void kernel_launch(void* const* d_in, const int* in_sizes, int n_in,
                              void* d_out, int out_size)
{
    const float* x    = (const float*)d_in[0];
    const float* y    = (const float*)d_in[1];
    const float* mask = (const float*)d_in[2];
    const float* Wq   = (const float*)d_in[3];
    const float* bq   = (const float*)d_in[4];
    const float* Wk   = (const float*)d_in[5];
    const float* bk   = (const float*)d_in[6];
    const float* Wv   = (const float*)d_in[7];
    const float* bv   = (const float*)d_in[8];
    const float* Wo   = (const float*)d_in[9];
    const float* bo   = (const float*)d_in[10];
    float* out = (float*)d_out;

    __nv_bfloat16 *qh, *ql, *kh, *kl, *vh, *vl;
    float* ga;
    cudaGetSymbolAddress((void**)&qh, g_qh);
    cudaGetSymbolAddress((void**)&ql, g_ql);
    cudaGetSymbolAddress((void**)&kh, g_kh);
    cudaGetSymbolAddress((void**)&kl, g_kl);
    cudaGetSymbolAddress((void**)&vh, g_vh);
    cudaGetSymbolAddress((void**)&vl, g_vl);
    cudaGetSymbolAddress((void**)&ga, g_attn);

    cudaFuncSetAttribute(flash_attn_mma,
                         cudaFuncAttributeMaxDynamicSharedMemorySize, ATT_SMEM);

    dim3 ggrid(D_MODEL / BN, M_TOTAL / BM);     // (8, 32)
    gemm_mma<true><<<ggrid, 256>>>(x, Wq, bq, nullptr, qh, ql);
    gemm_mma<true><<<ggrid, 256>>>(y, Wk, bk, nullptr, kh, kl);
    gemm_mma<true><<<ggrid, 256>>>(y, Wv, bv, nullptr, vh, vl);

    dim3 agrid(BATCH * HEADS, SEQ / 128);       // (32, 16)
    flash_attn_mma<<<agrid, 256, ATT_SMEM>>>(mask);

    gemm_mma<false><<<ggrid, 256>>>(ga, Wo, bo, out, nullptr, nullptr);
}

// round 11
// speedup vs baseline: 2.6533x; 1.2108x over previous
#include <cuda_runtime.h>
#include <cuda_bf16.h>
#include <cstdint>
#include <math.h>

// Problem constants (fixed by the dataset)
#define D_MODEL   1024
#define HEADS     16
#define HEAD_DIM  64
#define BATCH     2
#define SEQ       2048
#define M_TOTAL   (BATCH * SEQ)       // 4096 rows for projection GEMMs

// Scratch: device globals (no allocations allowed)
__device__ __nv_bfloat16 g_qh[M_TOTAL * D_MODEL];
__device__ __nv_bfloat16 g_ql[M_TOTAL * D_MODEL];
__device__ __nv_bfloat16 g_kh[M_TOTAL * D_MODEL];
__device__ __nv_bfloat16 g_kl[M_TOTAL * D_MODEL];
__device__ __nv_bfloat16 g_vh[M_TOTAL * D_MODEL];
__device__ __nv_bfloat16 g_vl[M_TOTAL * D_MODEL];
__device__ float         g_attn[M_TOTAL * D_MODEL];

// ============================================================================
// Warp-level MMA helpers (mma.sync + ldmatrix + cp.async — base sm_103)
// ============================================================================
__device__ __forceinline__ uint32_t smem_u32(const void* p) {
    uint32_t a;
    asm("{ .reg .u64 t; cvta.to.shared.u64 t, %1; cvt.u32.u64 %0, t; }"
        : "=r"(a) : "l"(p));
    return a;
}

__device__ __forceinline__ void ldm_x4(uint32_t* r, uint32_t addr) {
    asm volatile("ldmatrix.sync.aligned.m8n8.x4.shared.b16 {%0,%1,%2,%3}, [%4];"
                 : "=r"(r[0]), "=r"(r[1]), "=r"(r[2]), "=r"(r[3]) : "r"(addr));
}

__device__ __forceinline__ void ldm_x4_trans(uint32_t* r, uint32_t addr) {
    asm volatile("ldmatrix.sync.aligned.m8n8.x4.trans.shared.b16 {%0,%1,%2,%3}, [%4];"
                 : "=r"(r[0]), "=r"(r[1]), "=r"(r[2]), "=r"(r[3]) : "r"(addr));
}

// D += A(16x16) * B(16x8)  bf16 inputs, fp32 accum
__device__ __forceinline__ void mma16816(float* d, const uint32_t* a, const uint32_t* b) {
    asm volatile(
        "mma.sync.aligned.m16n8k16.row.col.f32.bf16.bf16.f32 "
        "{%0,%1,%2,%3}, {%4,%5,%6,%7}, {%8,%9}, {%0,%1,%2,%3};"
        : "+f"(d[0]), "+f"(d[1]), "+f"(d[2]), "+f"(d[3])
        : "r"(a[0]), "r"(a[1]), "r"(a[2]), "r"(a[3]), "r"(b[0]), "r"(b[1]));
}

__device__ __forceinline__ void cpa16(uint32_t dst, const void* src) {
    asm volatile("cp.async.ca.shared.global [%0], [%1], 16;"
                 :: "r"(dst), "l"(src) : "memory");
}
#define CP_COMMIT() asm volatile("cp.async.commit_group;" ::: "memory")
#define CP_WAIT0()  asm volatile("cp.async.wait_group 0;" ::: "memory")

// Convert 4 fp32 -> 4 bf16 hi + 4 bf16 lo (residual), store 8B to each tile
__device__ __forceinline__ void cvt_split_store(char* hi_tile, char* lo_tile,
                                                uint32_t off, float4 v) {
    uint32_t h01, h23, l01, l23;
    asm("cvt.rn.bf16x2.f32 %0, %1, %2;" : "=r"(h01) : "f"(v.y), "f"(v.x));
    asm("cvt.rn.bf16x2.f32 %0, %1, %2;" : "=r"(h23) : "f"(v.w), "f"(v.z));
    float r0 = v.x - __uint_as_float(h01 << 16);
    float r1 = v.y - __uint_as_float(h01 & 0xFFFF0000u);
    float r2 = v.z - __uint_as_float(h23 << 16);
    float r3 = v.w - __uint_as_float(h23 & 0xFFFF0000u);
    asm("cvt.rn.bf16x2.f32 %0, %1, %2;" : "=r"(l01) : "f"(r1), "f"(r0));
    asm("cvt.rn.bf16x2.f32 %0, %1, %2;" : "=r"(l23) : "f"(r3), "f"(r2));
    *(uint2*)(hi_tile + off) = make_uint2(h01, h23);
    *(uint2*)(lo_tile + off) = make_uint2(l01, l23);
}

// Pack two fp32 -> bf16x2 (lo half = first arg) + residual pair
__device__ __forceinline__ void pack_split(float p0, float p1, uint32_t& h, uint32_t& l) {
    asm("cvt.rn.bf16x2.f32 %0, %1, %2;" : "=r"(h) : "f"(p1), "f"(p0));
    float r0 = p0 - __uint_as_float(h << 16);
    float r1 = p1 - __uint_as_float(h & 0xFFFF0000u);
    asm("cvt.rn.bf16x2.f32 %0, %1, %2;" : "=r"(l) : "f"(r1), "f"(r0));
}

// ============================================================================
// GEMM: C[M,N] = A[M,K] @ W[N,K]^T + bias   (M=4096, N=K=1024)  [validated R5]
// SPLIT=true: write hi/lo bf16 arrays. SPLIT=false: write fp32 C.
// ============================================================================
#define BM 128
#define BN 128
#define BK 32
#define KITERS (D_MODEL / BK)       // 32
#define LDT 40                       // tile row stride in halves (80 bytes)
#define TILE_BYTES (128 * LDT * 2)   // 10240

template<bool SPLIT>
__global__ __launch_bounds__(256) void gemm_mma(
    const float* __restrict__ A,
    const float* __restrict__ W,
    const float* __restrict__ bias,
    float* __restrict__ C,
    __nv_bfloat16* __restrict__ Chi,
    __nv_bfloat16* __restrict__ Clo)
{
    __shared__ char sm[4 * TILE_BYTES];   // As_hi, As_lo, Bs_hi, Bs_lo
    char* As_hi = sm;
    char* As_lo = sm + TILE_BYTES;
    char* Bs_hi = sm + 2 * TILE_BYTES;
    char* Bs_lo = sm + 3 * TILE_BYTES;

    const int tid    = threadIdx.x;
    const int lane   = tid & 31;
    const int wid    = tid >> 5;
    const int warp_m = wid & 3;
    const int warp_n = wid >> 2;
    const int bm     = blockIdx.y;
    const int bn     = blockIdx.x;

    const float* Ag = A + (size_t)bm * BM * D_MODEL;
    const float* Wg = W + (size_t)bn * BN * D_MODEL;

    uint32_t st_off[4];
    uint32_t gl_off[4];
    #pragma unroll
    for (int i = 0; i < 4; i++) {
        int f = tid + i * 256;
        int r = f >> 3, c4 = (f & 7) * 4;
        st_off[i] = (uint32_t)(r * (LDT * 2) + c4 * 2);
        gl_off[i] = (uint32_t)(r * D_MODEL + c4);
    }

    const uint32_t a_base = smem_u32(As_hi);
    const uint32_t a_off =
        (uint32_t)((warp_m * 32 + (lane & 7) + ((lane >> 3) & 1) * 8) * (LDT * 2)
                   + (lane >> 4) * 16);
    const uint32_t b_off =
        (uint32_t)((warp_n * 64 + (lane & 7)) * (LDT * 2) + (lane >> 3) * 16);

    float acc[2][8][4];
    #pragma unroll
    for (int mt = 0; mt < 2; mt++)
        #pragma unroll
        for (int nt = 0; nt < 8; nt++)
            #pragma unroll
            for (int j = 0; j < 4; j++) acc[mt][nt][j] = 0.0f;

    float4 pa[4], pb[4];
    #pragma unroll
    for (int i = 0; i < 4; i++) {
        pa[i] = *(const float4*)(Ag + gl_off[i]);
        pb[i] = *(const float4*)(Wg + gl_off[i]);
    }

    for (int it = 0; it < KITERS; it++) {
        #pragma unroll
        for (int i = 0; i < 4; i++) {
            cvt_split_store(As_hi, As_lo, st_off[i], pa[i]);
            cvt_split_store(Bs_hi, Bs_lo, st_off[i], pb[i]);
        }
        __syncthreads();

        if (it + 1 < KITERS) {
            const uint32_t g = (uint32_t)((it + 1) * BK);
            #pragma unroll
            for (int i = 0; i < 4; i++) {
                pa[i] = *(const float4*)(Ag + gl_off[i] + g);
                pb[i] = *(const float4*)(Wg + gl_off[i] + g);
            }
        }

        uint32_t ah[2][2][4], al[2][2][4];
        #pragma unroll
        for (int ks = 0; ks < 2; ks++)
            #pragma unroll
            for (int mt = 0; mt < 2; mt++) {
                uint32_t off = a_off + (uint32_t)(mt * 16 * (LDT * 2) + ks * 32);
                ldm_x4(ah[ks][mt], a_base + off);
                ldm_x4(al[ks][mt], a_base + TILE_BYTES + off);
            }

        #pragma unroll
        for (int nt = 0; nt < 8; nt++) {
            uint32_t off = b_off + (uint32_t)(nt * 8 * (LDT * 2));
            uint32_t bh[4], bl[4];
            ldm_x4(bh, a_base + 2 * TILE_BYTES + off);
            ldm_x4(bl, a_base + 3 * TILE_BYTES + off);
            #pragma unroll
            for (int ks = 0; ks < 2; ks++)
                #pragma unroll
                for (int mt = 0; mt < 2; mt++) {
                    mma16816(acc[mt][nt], ah[ks][mt], bh + ks * 2);
                    mma16816(acc[mt][nt], ah[ks][mt], bl + ks * 2);
                    mma16816(acc[mt][nt], al[ks][mt], bh + ks * 2);
                }
        }
        __syncthreads();
    }

    const int lrow = lane >> 2;
    const int lcol = (lane & 3) * 2;
    #pragma unroll
    for (int mt = 0; mt < 2; mt++) {
        const int r0 = bm * BM + warp_m * 32 + mt * 16 + lrow;
        #pragma unroll
        for (int nt = 0; nt < 8; nt++) {
            const int cg = bn * BN + warp_n * 64 + nt * 8 + lcol;
            const float b0 = bias[cg], b1 = bias[cg + 1];
            float c00 = acc[mt][nt][0] + b0, c01 = acc[mt][nt][1] + b1;
            float c10 = acc[mt][nt][2] + b0, c11 = acc[mt][nt][3] + b1;
            if (SPLIT) {
                uint32_t h0, l0, h1, l1;
                pack_split(c00, c01, h0, l0);
                pack_split(c10, c11, h1, l1);
                *(uint32_t*)(Chi + (size_t)r0 * D_MODEL + cg)       = h0;
                *(uint32_t*)(Clo + (size_t)r0 * D_MODEL + cg)       = l0;
                *(uint32_t*)(Chi + (size_t)(r0 + 8) * D_MODEL + cg) = h1;
                *(uint32_t*)(Clo + (size_t)(r0 + 8) * D_MODEL + cg) = l1;
            } else {
                *(float2*)(C + (size_t)r0 * D_MODEL + cg)       = make_float2(c00, c01);
                *(float2*)(C + (size_t)(r0 + 8) * D_MODEL + cg) = make_float2(c10, c11);
            }
        }
    }
}

// ============================================================================
// Flash attention on tensor cores. Inputs pre-split bf16 hi/lo.
// Block: 128 q-rows x one (b,h). 8 warps, warp owns 16 rows.
// KV tiles of 64, cp.async double-buffered. Q staging region is ALIASED with
// KV buffer 1 (Q is register-resident after the hoist) -> 72KB smem, and
// __launch_bounds__(256,2) -> 2 CTAs/SM resident.  Grid: (B*H, SEQ/128).
// ============================================================================
#define LDB     144                  // smem row stride bytes (72 halves)
#define KV_KH   0
#define KV_KL   9216
#define KV_VH   18432
#define KV_VL   27648
#define KVBUF   36864                // per-buffer size
#define OFF_QH  KVBUF                // Q staged in buffer 1, recycled after hoist
#define OFF_QL  (KVBUF + 18432)
#define ATT_SMEM (2 * KVBUF)         // 73728

__device__ __forceinline__ void stage_kv_tile(
    uint32_t bufb,
    const __nv_bfloat16* kh, const __nv_bfloat16* kl,
    const __nv_bfloat16* vh, const __nv_bfloat16* vl,
    int tid)
{
    #pragma unroll
    for (int i = 0; i < 2; i++) {
        int f = tid + i * 256;
        int r = f >> 3, c = f & 7;
        uint32_t so = (uint32_t)(r * LDB + c * 16);
        size_t go = (size_t)r * D_MODEL + c * 8;
        cpa16(bufb + KV_KH + so, kh + go);
        cpa16(bufb + KV_KL + so, kl + go);
        cpa16(bufb + KV_VH + so, vh + go);
        cpa16(bufb + KV_VL + so, vl + go);
    }
}

__global__ void __launch_bounds__(256, 2) flash_attn_mma(const float* __restrict__ mask)
{
    extern __shared__ char sm[];
    const uint32_t smb = smem_u32(sm);
    const int tid  = threadIdx.x;
    const int lane = tid & 31;
    const int wid  = tid >> 5;
    const int bh   = blockIdx.x;
    const int b    = bh >> 4;            // / HEADS
    const int h    = bh & 15;
    const int q0   = blockIdx.y * 128;

    const size_t qrow0 = (size_t)(b * SEQ + q0);
    const size_t krow0 = (size_t)b * SEQ;
    const __nv_bfloat16* Qh = g_qh + qrow0 * D_MODEL + h * HEAD_DIM;
    const __nv_bfloat16* Ql = g_ql + qrow0 * D_MODEL + h * HEAD_DIM;
    const __nv_bfloat16* Kh = g_kh + krow0 * D_MODEL + h * HEAD_DIM;
    const __nv_bfloat16* Kl = g_kl + krow0 * D_MODEL + h * HEAD_DIM;
    const __nv_bfloat16* Vh = g_vh + krow0 * D_MODEL + h * HEAD_DIM;
    const __nv_bfloat16* Vl = g_vl + krow0 * D_MODEL + h * HEAD_DIM;
    const float* Mg = mask + (qrow0) * SEQ;

    // Stage Q (into buffer-1 region) + KV tile 0 (buffer 0)
    #pragma unroll
    for (int i = 0; i < 4; i++) {
        int f = tid + i * 256;
        int r = f >> 3, c = f & 7;
        uint32_t so = (uint32_t)(r * LDB + c * 16);
        size_t go = (size_t)r * D_MODEL + c * 8;
        cpa16(smb + OFF_QH + so, Qh + go);
        cpa16(smb + OFF_QL + so, Ql + go);
    }
    stage_kv_tile(smb, Kh, Kl, Vh, Vl, tid);
    CP_COMMIT();
    CP_WAIT0();
    __syncthreads();

    // Hoist Q fragments to registers (whole KV loop)
    const int qr = wid * 16;
    uint32_t ah[4][4], al[4][4];
    {
        uint32_t base = smb + (uint32_t)((qr + (lane & 15)) * LDB + (lane >> 4) * 16);
        #pragma unroll
        for (int ks = 0; ks < 4; ks++) {
            ldm_x4(ah[ks], base + OFF_QH + ks * 32);
            ldm_x4(al[ks], base + OFF_QL + ks * 32);
        }
    }
    __syncthreads();   // everyone done reading Q smem; buffer 1 is now free

    // Prefetch KV tile 1 into buffer 1 (recycled Q region)
    stage_kv_tile(smb + KVBUF, Kh + 64 * D_MODEL, Kl + 64 * D_MODEL,
                  Vh + 64 * D_MODEL, Vl + 64 * D_MODEL, tid);
    CP_COMMIT();

    const int lrow = lane >> 2;
    const int lcol = (lane & 3) * 2;
    const uint32_t kfrag = (uint32_t)((lane & 7) * LDB + (lane >> 3) * 16);

    float o[8][4];
    #pragma unroll
    for (int dt = 0; dt < 8; dt++)
        #pragma unroll
        for (int j = 0; j < 4; j++) o[dt][j] = 0.0f;
    float m0 = -1e30f, m8 = -1e30f, l0 = 0.0f, l8 = 0.0f;

    for (int kb = 0; kb < SEQ / 64; kb++) {
        if (kb > 0) {
            CP_WAIT0();
            __syncthreads();
        }
        if (kb >= 1 && kb + 1 < SEQ / 64) {
            size_t off = (size_t)(kb + 1) * 64 * D_MODEL;
            stage_kv_tile(smb + ((kb + 1) & 1) * KVBUF,
                          Kh + off, Kl + off, Vh + off, Vl + off, tid);
            CP_COMMIT();
        }
        const uint32_t bufb = smb + (kb & 1) * KVBUF;

        // S = Q K^T (3-pass hi/lo), warp tile 16x64
        float s[8][4];
        #pragma unroll
        for (int nt = 0; nt < 8; nt++)
            #pragma unroll
            for (int j = 0; j < 4; j++) s[nt][j] = 0.0f;

        #pragma unroll
        for (int nt = 0; nt < 8; nt++) {
            uint32_t ka = bufb + kfrag + (uint32_t)(nt * 8 * LDB);
            uint32_t kh[8], kl[8];
            ldm_x4(kh,     ka + KV_KH);
            ldm_x4(kh + 4, ka + KV_KH + 64);
            ldm_x4(kl,     ka + KV_KL);
            ldm_x4(kl + 4, ka + KV_KL + 64);
            #pragma unroll
            for (int ks = 0; ks < 4; ks++) {
                mma16816(s[nt], ah[ks], kh + ks * 2);
                mma16816(s[nt], ah[ks], kl + ks * 2);
                mma16816(s[nt], al[ks], kh + ks * 2);
            }
        }

        // Scale + mask + row max
        const float* mrow = Mg + (size_t)kb * 64;
        float tmax0 = -1e30f, tmax8 = -1e30f;
        #pragma unroll
        for (int nt = 0; nt < 8; nt++) {
            int c = nt * 8 + lcol;
            float2 mk0 = *(const float2*)(mrow + (size_t)(qr + lrow) * SEQ + c);
            float2 mk8 = *(const float2*)(mrow + (size_t)(qr + lrow + 8) * SEQ + c);
            s[nt][0] = fmaf(s[nt][0], 0.125f, (mk0.x - 1.0f) * 1e9f);
            s[nt][1] = fmaf(s[nt][1], 0.125f, (mk0.y - 1.0f) * 1e9f);
            s[nt][2] = fmaf(s[nt][2], 0.125f, (mk8.x - 1.0f) * 1e9f);
            s[nt][3] = fmaf(s[nt][3], 0.125f, (mk8.y - 1.0f) * 1e9f);
            tmax0 = fmaxf(tmax0, fmaxf(s[nt][0], s[nt][1]));
            tmax8 = fmaxf(tmax8, fmaxf(s[nt][2], s[nt][3]));
        }
        tmax0 = fmaxf(tmax0, __shfl_xor_sync(0xffffffffu, tmax0, 1));
        tmax0 = fmaxf(tmax0, __shfl_xor_sync(0xffffffffu, tmax0, 2));
        tmax8 = fmaxf(tmax8, __shfl_xor_sync(0xffffffffu, tmax8, 1));
        tmax8 = fmaxf(tmax8, __shfl_xor_sync(0xffffffffu, tmax8, 2));

        float mn0 = fmaxf(m0, tmax0), mn8 = fmaxf(m8, tmax8);
        float al0 = __expf(m0 - mn0), al8 = __expf(m8 - mn8);
        m0 = mn0; m8 = mn8;

        // exp, sums, and P fragments (hi/lo) in registers
        float sum0 = 0.0f, sum8 = 0.0f;
        uint32_t pah[4][4], pal[4][4];
        #pragma unroll
        for (int nt = 0; nt < 8; nt++) {
            float p0 = __expf(s[nt][0] - mn0);
            float p1 = __expf(s[nt][1] - mn0);
            float p2 = __expf(s[nt][2] - mn8);
            float p3 = __expf(s[nt][3] - mn8);
            sum0 += p0 + p1;
            sum8 += p2 + p3;
            int ks = nt >> 1, slot = (nt & 1) * 2;
            pack_split(p0, p1, pah[ks][slot],     pal[ks][slot]);
            pack_split(p2, p3, pah[ks][slot + 1], pal[ks][slot + 1]);
        }
        sum0 += __shfl_xor_sync(0xffffffffu, sum0, 1);
        sum0 += __shfl_xor_sync(0xffffffffu, sum0, 2);
        sum8 += __shfl_xor_sync(0xffffffffu, sum8, 1);
        sum8 += __shfl_xor_sync(0xffffffffu, sum8, 2);
        l0 = l0 * al0 + sum0;
        l8 = l8 * al8 + sum8;

        // Rescale O, then O += P @ V (3-pass hi/lo, V via ldmatrix.trans)
        #pragma unroll
        for (int dt = 0; dt < 8; dt++) {
            o[dt][0] *= al0; o[dt][1] *= al0;
            o[dt][2] *= al8; o[dt][3] *= al8;
        }
        #pragma unroll
        for (int dt = 0; dt < 8; dt++) {
            uint32_t va = bufb + (uint32_t)(lane * LDB + dt * 16);
            uint32_t vh[8], vl[8];
            ldm_x4_trans(vh,     va + KV_VH);
            ldm_x4_trans(vh + 4, va + KV_VH + 32 * LDB);
            ldm_x4_trans(vl,     va + KV_VL);
            ldm_x4_trans(vl + 4, va + KV_VL + 32 * LDB);
            #pragma unroll
            for (int ks = 0; ks < 4; ks++) {
                mma16816(o[dt], pah[ks], vh + ks * 2);
                mma16816(o[dt], pah[ks], vl + ks * 2);
                mma16816(o[dt], pal[ks], vh + ks * 2);
            }
        }
    }

    // Normalize and store
    const float inv0 = 1.0f / l0;
    const float inv8 = 1.0f / l8;
    float* Og = g_attn + (qrow0 + qr) * D_MODEL + h * HEAD_DIM;
    #pragma unroll
    for (int dt = 0; dt < 8; dt++) {
        int c = dt * 8 + lcol;
        float2 v0 = make_float2(o[dt][0] * inv0, o[dt][1] * inv0);
        float2 v1 = make_float2(o[dt][2] * inv8, o[dt][3] * inv8);
        *(float2*)(Og + (size_t)lrow * D_MODEL + c)       = v0;
        *(float2*)(Og + (size_t)(lrow + 8) * D_MODEL + c) = v1;
    }
}

// ----------------------------------------------------------------------------
extern "C" void kernel_launch(void* const* d_in, const int* in_sizes, int n_in,
                              void* d_out, int out_size)
{
    const float* x    = (const float*)d_in[0];
    const float* y    = (const float*)d_in[1];
    const float* mask = (const float*)d_in[2];
    const float* Wq   = (const float*)d_in[3];
    const float* bq   = (const float*)d_in[4];
    const float* Wk   = (const float*)d_in[5];
    const float* bk   = (const float*)d_in[6];
    const float* Wv   = (const float*)d_in[7];
    const float* bv   = (const float*)d_in[8];
    const float* Wo   = (const float*)d_in[9];
    const float* bo   = (const float*)d_in[10];
    float* out = (float*)d_out;

    __nv_bfloat16 *qh, *ql, *kh, *kl, *vh, *vl;
    float* ga;
    cudaGetSymbolAddress((void**)&qh, g_qh);
    cudaGetSymbolAddress((void**)&ql, g_ql);
    cudaGetSymbolAddress((void**)&kh, g_kh);
    cudaGetSymbolAddress((void**)&kl, g_kl);
    cudaGetSymbolAddress((void**)&vh, g_vh);
    cudaGetSymbolAddress((void**)&vl, g_vl);
    cudaGetSymbolAddress((void**)&ga, g_attn);

    cudaFuncSetAttribute(flash_attn_mma,
                         cudaFuncAttributeMaxDynamicSharedMemorySize, ATT_SMEM);

    dim3 ggrid(D_MODEL / BN, M_TOTAL / BM);     // (8, 32)
    gemm_mma<true><<<ggrid, 256>>>(x, Wq, bq, nullptr, qh, ql);
    gemm_mma<true><<<ggrid, 256>>>(y, Wk, bk, nullptr, kh, kl);
    gemm_mma<true><<<ggrid, 256>>>(y, Wv, bv, nullptr, vh, vl);

    dim3 agrid(BATCH * HEADS, SEQ / 128);       // (32, 16)
    flash_attn_mma<<<agrid, 256, ATT_SMEM>>>(mask);

    gemm_mma<false><<<ggrid, 256>>>(ga, Wo, bo, out, nullptr, nullptr);
}